// round 5
// baseline (speedup 1.0000x reference)
#include <cuda_runtime.h>
#include <cstdint>
#include <math.h>

#define H       256
#define FH      1024
#define NNODE   20000
#define NEDGE   160000
#define NLG     640000

// ---------------- scratch (static device memory; no allocations) ----------------
__device__ float g_x[2][(size_t)NNODE * H];
__device__ float g_lg[2][(size_t)NEDGE * H];
__device__ float g_fn[(size_t)NNODE * H];
__device__ float g_fe[(size_t)NEDGE * H];
__device__ float g_z[4][(size_t)NEDGE * H];
__device__ float g_out1[(size_t)NEDGE * H];

// tf32-pre-rounded weights
#define OFF_WSELF 0
#define OFF_WKHOP (OFF_WSELF + 4 * H * H)
#define OFF_WFUSE (OFF_WKHOP + 16 * H * H)
#define OFF_WFF1  (OFF_WFUSE + 4 * H * H)
#define OFF_WFF2  (OFF_WFF1 + 4 * H * FH)
#define WBUF_TOT  (OFF_WFF2 + 4 * FH * H)
__device__ float g_wbuf[WBUF_TOT];

// CSR structures
__device__ int g_rp_nd[NNODE + 1];
__device__ int g_ci_nd[NEDGE];
__device__ int g_rp_fn[NNODE + 1];
__device__ int g_ci_fn[2 * NEDGE];
__device__ int g_rp_lg[NEDGE + 1];
__device__ int g_ci_lg[NLG];
__device__ int g_cnt[NEDGE];
__device__ int g_cur[NEDGE];
__device__ int g_bs[1024];

__device__ __forceinline__ float gelu_exact(float v) {
    return 0.5f * v * (1.0f + erff(v * 0.70710678118654752f));
}

__device__ __forceinline__ float f2tf32f(float f) {
    uint32_t r;
    asm("cvt.rna.tf32.f32 %0, %1;" : "=r"(r) : "f"(f));
    return __uint_as_float(r);
}

__device__ __forceinline__ void mma_tf32(float* c, const uint32_t* a, const uint32_t* b) {
    asm volatile(
        "mma.sync.aligned.m16n8k8.row.col.f32.tf32.tf32.f32 "
        "{%0,%1,%2,%3}, {%4,%5,%6,%7}, {%8,%9}, {%0,%1,%2,%3};"
        : "+f"(c[0]), "+f"(c[1]), "+f"(c[2]), "+f"(c[3])
        : "r"(a[0]), "r"(a[1]), "r"(a[2]), "r"(a[3]), "r"(b[0]), "r"(b[1]));
}

// ---------------- CSR build kernels ----------------

__global__ void hist_kernel(const int* __restrict__ key, int* cnt, int n) {
    int i = blockIdx.x * 256 + threadIdx.x;
    if (i < n) atomicAdd(&cnt[__ldg(key + i)], 1);
}

__global__ void scan1_kernel(const int* __restrict__ in, int* __restrict__ out,
                             int* __restrict__ bsums, int n) {
    __shared__ int sh[1024];
    int i = blockIdx.x * 1024 + threadIdx.x;
    int v = (i < n) ? in[i] : 0;
    sh[threadIdx.x] = v;
    __syncthreads();
#pragma unroll
    for (int o = 1; o < 1024; o <<= 1) {
        int t = (threadIdx.x >= o) ? sh[threadIdx.x - o] : 0;
        __syncthreads();
        sh[threadIdx.x] += t;
        __syncthreads();
    }
    if (i < n) out[i] = sh[threadIdx.x] - v;     // exclusive
    if (threadIdx.x == 1023) bsums[blockIdx.x] = sh[1023];
}

__global__ void scan2_kernel(int* bsums, int nb) {
    __shared__ int sh[1024];
    int v = (threadIdx.x < nb) ? bsums[threadIdx.x] : 0;
    sh[threadIdx.x] = v;
    __syncthreads();
#pragma unroll
    for (int o = 1; o < 1024; o <<= 1) {
        int t = (threadIdx.x >= o) ? sh[threadIdx.x - o] : 0;
        __syncthreads();
        sh[threadIdx.x] += t;
        __syncthreads();
    }
    if (threadIdx.x < nb) bsums[threadIdx.x] = sh[threadIdx.x] - v;  // exclusive
}

__global__ void scan3_kernel(int* __restrict__ out, const int* __restrict__ bsums,
                             const int* __restrict__ cnt, int n) {
    int i = blockIdx.x * 1024 + threadIdx.x;
    if (i < n) {
        int v = out[i] + bsums[i >> 10];
        out[i] = v;
        if (i == n - 1) out[n] = v + cnt[i];
    }
}

__global__ void fill_kernel(const int* __restrict__ key, const int* __restrict__ val,
                            int* cursor, int* __restrict__ ci, int n) {
    int i = blockIdx.x * 256 + threadIdx.x;
    if (i >= n) return;
    int pos = atomicAdd(&cursor[__ldg(key + i)], 1);
    ci[pos] = val ? __ldg(val + i) : i;
}

// ---------------- small kernels ----------------

__global__ void cvt_kernel(const float* __restrict__ in, float* __restrict__ out, int n4) {
    int i = blockIdx.x * 256 + threadIdx.x;
    if (i >= n4) return;
    float4 v = ((const float4*)in)[i];
    v.x = f2tf32f(v.x); v.y = f2tf32f(v.y); v.z = f2tf32f(v.z); v.w = f2tf32f(v.w);
    ((float4*)out)[i] = v;
}

__global__ void embed_kernel(const float* __restrict__ rel, const int* __restrict__ feat,
                             float* __restrict__ out) {
    int gid = blockIdx.x * blockDim.x + threadIdx.x;
    int e = gid >> 6;
    if (e >= NEDGE) return;
    int c = (gid & 63) << 2;
    int r = __ldg(feat + e);
    float4 v = *(const float4*)(rel + (size_t)r * H + c);
    v.x = f2tf32f(v.x); v.y = f2tf32f(v.y); v.z = f2tf32f(v.z); v.w = f2tf32f(v.w);
    *(float4*)(out + (size_t)e * H + c) = v;
}

__global__ void gather2_kernel(const float* __restrict__ x, const int* __restrict__ s,
                               const int* __restrict__ d, float* __restrict__ out, int n) {
    int gid = blockIdx.x * blockDim.x + threadIdx.x;
    int e = gid >> 6;
    if (e >= n) return;
    int c = (gid & 63) << 2;
    int si = __ldg(s + e), di = __ldg(d + e);
    float4 a = *(const float4*)(x + (size_t)si * H + c);
    float4 b = *(const float4*)(x + (size_t)di * H + c);
    a.x = f2tf32f(a.x + b.x); a.y = f2tf32f(a.y + b.y);
    a.z = f2tf32f(a.z + b.z); a.w = f2tf32f(a.w + b.w);
    *(float4*)(out + (size_t)e * H + c) = a;
}

// CSR gather segment-sum: out[r] = tf32( sum rows[ci[j]] )
__global__ void segsum_kernel(const float* __restrict__ rows, const int* __restrict__ rp,
                              const int* __restrict__ ci, float* __restrict__ out, int nseg) {
    int row = blockIdx.x * 8 + (threadIdx.x >> 5);
    if (row >= nseg) return;
    int lane = threadIdx.x & 31;
    int beg = __ldg(rp + row), end = __ldg(rp + row + 1);
    float a[8] = {0.f, 0.f, 0.f, 0.f, 0.f, 0.f, 0.f, 0.f};
    for (int j = beg; j < end; j++) {
        const float* p = rows + (size_t)__ldg(ci + j) * H + lane * 8;
        float4 v0 = ((const float4*)p)[0];
        float4 v1 = ((const float4*)p)[1];
        a[0] += v0.x; a[1] += v0.y; a[2] += v0.z; a[3] += v0.w;
        a[4] += v1.x; a[5] += v1.y; a[6] += v1.z; a[7] += v1.w;
    }
#pragma unroll
    for (int i = 0; i < 8; i++) a[i] = f2tf32f(a[i]);
    float* po = out + (size_t)row * H + lane * 8;
    ((float4*)po)[0] = make_float4(a[0], a[1], a[2], a[3]);
    ((float4*)po)[1] = make_float4(a[4], a[5], a[6], a[7]);
}

// ================= GEMM1 + LN1 fused =================
// out1 = tf32( LN( xres + gelu( sum_j A_j @ W_j + sum_j bias_j ) ) )
// BM=64, BN=256 (full rows), K = 6 x 256, 256 threads.

#define G_ASTR 36
#define G_BSTR 264
#define G_AST (64 * G_ASTR)       // 2304
#define G_BST (32 * G_BSTR)       // 8448
#define G1_SMEM_FLOATS (2 * G_AST + 2 * G_BST + 3 * 256 + 256)
#define G1_SMEM_BYTES (G1_SMEM_FLOATS * 4)

struct G1Args {
    const float* A[6];
    const float* W[6];
    const float* Bias[6];
    const float* xres;
    const float* gamma;
    const float* beta;
};

__global__ void __launch_bounds__(256, 2)
gemm1_ln_kernel(G1Args args, int M, float* __restrict__ out) {
    extern __shared__ float sm[];
    float* As = sm;
    float* Bs = sm + 2 * G_AST;
    float* bias_s = Bs + 2 * G_BST;
    float* gs = bias_s + 256;
    float* bt = gs + 256;
    float* lnS = bt + 256;
    float* lnQ = lnS + 128;
    float* xs = sm;                 // alias; reused after mainloop, stride 264

    int tid = threadIdx.x;
    int bm = blockIdx.x * 64;

    {
        float b = 0.f;
#pragma unroll
        for (int j = 0; j < 6; j++) b += __ldg(args.Bias[j] + tid);
        bias_s[tid] = b;
        gs[tid] = __ldg(args.gamma + tid);
        bt[tid] = __ldg(args.beta + tid);
    }

    uint32_t a_base = (uint32_t)__cvta_generic_to_shared(As);
    uint32_t b_base = (uint32_t)__cvta_generic_to_shared(Bs);

    int warp = tid >> 5, lane = tid & 31, g = lane >> 2, t = lane & 3;
    int wm = (warp >> 1) * 16;
    int wN = warp & 1;
    int wn = wN * 128;

    float acc[16][4];
#pragma unroll
    for (int nf = 0; nf < 16; nf++)
#pragma unroll
        for (int i = 0; i < 4; i++) acc[nf][i] = 0.f;

    auto issue = [&](int tt, int buf) {
        int j = tt >> 3;
        int kk = (tt & 7) * 32;
        const float* A = args.A[j];
        const float* W = args.W[j];
#pragma unroll
        for (int i = 0; i < 2; i++) {
            int idx = tid + i * 256;
            int r = idx >> 3, kv = (idx & 7) << 2;
            int row = bm + r;
            uint32_t dst = a_base + (uint32_t)((buf * G_AST + r * G_ASTR + kv) * 4);
            const float* src = A + (size_t)row * H + kk + kv;
            int sz = (row < M) ? 16 : 0;
            asm volatile("cp.async.cg.shared.global [%0], [%1], 16, %2;\n"
                         :: "r"(dst), "l"(src), "r"(sz));
        }
#pragma unroll
        for (int i = 0; i < 8; i++) {
            int idx = tid + i * 256;
            int r = idx >> 6, nv = (idx & 63) << 2;
            uint32_t dst = b_base + (uint32_t)((buf * G_BST + r * G_BSTR + nv) * 4);
            const float* src = W + (size_t)(kk + r) * H + nv;
            asm volatile("cp.async.cg.shared.global [%0], [%1], 16;\n"
                         :: "r"(dst), "l"(src));
        }
        asm volatile("cp.async.commit_group;\n");
    };

    issue(0, 0);
    for (int tt = 0; tt < 48; tt++) {
        if (tt + 1 < 48) {
            issue(tt + 1, (tt + 1) & 1);
            asm volatile("cp.async.wait_group 1;\n");
        } else {
            asm volatile("cp.async.wait_group 0;\n");
        }
        __syncthreads();
        const float* Ab = As + (tt & 1) * G_AST;
        const float* Bb = Bs + (tt & 1) * G_BST;
#pragma unroll
        for (int ks = 0; ks < 4; ks++) {
            int k0 = ks * 8;
            uint32_t a[4];
            a[0] = __float_as_uint(Ab[(wm + g) * G_ASTR + k0 + t]);
            a[1] = __float_as_uint(Ab[(wm + 8 + g) * G_ASTR + k0 + t]);
            a[2] = __float_as_uint(Ab[(wm + g) * G_ASTR + k0 + t + 4]);
            a[3] = __float_as_uint(Ab[(wm + 8 + g) * G_ASTR + k0 + t + 4]);
#pragma unroll
            for (int nf = 0; nf < 16; nf++) {
                uint32_t b[2];
                b[0] = __float_as_uint(Bb[(k0 + t) * G_BSTR + wn + nf * 8 + g]);
                b[1] = __float_as_uint(Bb[(k0 + t + 4) * G_BSTR + wn + nf * 8 + g]);
                mma_tf32(acc[nf], a, b);
            }
        }
        __syncthreads();
    }

    // cooperative residual tile load into xs (stride 264)
#pragma unroll
    for (int i = 0; i < 16; i++) {
        int idx = tid + i * 256;
        int r = idx >> 6, cv = (idx & 63) << 2;
        int row = bm + r;
        float4 v = make_float4(0.f, 0.f, 0.f, 0.f);
        if (row < M) v = *(const float4*)(args.xres + (size_t)row * H + cv);
        *(float4*)(xs + r * 264 + cv) = v;
    }
    __syncthreads();

    int row0 = wm + g, row1 = wm + 8 + g;
    float s0 = 0.f, q0 = 0.f, s1 = 0.f, q1 = 0.f;
#pragma unroll
    for (int nf = 0; nf < 16; nf++) {
        int col = wn + nf * 8 + 2 * t;
        float t0 = xs[row0 * 264 + col]     + gelu_exact(acc[nf][0] + bias_s[col]);
        float t1 = xs[row0 * 264 + col + 1] + gelu_exact(acc[nf][1] + bias_s[col + 1]);
        float t2 = xs[row1 * 264 + col]     + gelu_exact(acc[nf][2] + bias_s[col]);
        float t3 = xs[row1 * 264 + col + 1] + gelu_exact(acc[nf][3] + bias_s[col + 1]);
        acc[nf][0] = t0; acc[nf][1] = t1; acc[nf][2] = t2; acc[nf][3] = t3;
        s0 += t0 + t1; q0 += t0 * t0 + t1 * t1;
        s1 += t2 + t3; q1 += t2 * t2 + t3 * t3;
    }
#pragma unroll
    for (int o = 1; o <= 2; o <<= 1) {
        s0 += __shfl_xor_sync(0xffffffffu, s0, o);
        q0 += __shfl_xor_sync(0xffffffffu, q0, o);
        s1 += __shfl_xor_sync(0xffffffffu, s1, o);
        q1 += __shfl_xor_sync(0xffffffffu, q1, o);
    }
    if (t == 0) {
        lnS[row0 * 2 + wN] = s0; lnQ[row0 * 2 + wN] = q0;
        lnS[row1 * 2 + wN] = s1; lnQ[row1 * 2 + wN] = q1;
    }
    __syncthreads();
    float S0 = lnS[row0 * 2] + lnS[row0 * 2 + 1];
    float Q0 = lnQ[row0 * 2] + lnQ[row0 * 2 + 1];
    float S1 = lnS[row1 * 2] + lnS[row1 * 2 + 1];
    float Q1 = lnQ[row1 * 2] + lnQ[row1 * 2 + 1];
    float m0 = S0 * (1.f / H), v0 = Q0 * (1.f / H) - m0 * m0, r0 = rsqrtf(v0 + 1e-5f);
    float m1 = S1 * (1.f / H), v1 = Q1 * (1.f / H) - m1 * m1, r1 = rsqrtf(v1 + 1e-5f);
    bool ok0 = (bm + row0) < M, ok1 = (bm + row1) < M;
#pragma unroll
    for (int nf = 0; nf < 16; nf++) {
        int col = wn + nf * 8 + 2 * t;
        float o0 = f2tf32f((acc[nf][0] - m0) * r0 * gs[col]     + bt[col]);
        float o1 = f2tf32f((acc[nf][1] - m0) * r0 * gs[col + 1] + bt[col + 1]);
        float o2 = f2tf32f((acc[nf][2] - m1) * r1 * gs[col]     + bt[col]);
        float o3 = f2tf32f((acc[nf][3] - m1) * r1 * gs[col + 1] + bt[col + 1]);
        if (ok0) *(float2*)(out + (size_t)(bm + row0) * H + col) = make_float2(o0, o1);
        if (ok1) *(float2*)(out + (size_t)(bm + row1) * H + col) = make_float2(o2, o3);
    }
}

// ================= fused FFN + LN2 =================
// out = LN( out1 + gelu(out1 @ w1 + b1) @ w2 + b2 ), out1 tile held in smem.
// BM=64, 512 threads, FH chunked by 128 with the GELU intermediate in smem.

#define F_XSTR 260
#define F_HSTR 132
#define F_B1STR 136
#define F_B1ST (32 * F_B1STR)     // 4352
#define F_B2STR 264
#define F_B2ST (32 * F_B2STR)     // 8448
#define F_SMEM_FLOATS (64 * F_XSTR + 64 * F_HSTR + 2 * F_B2ST + 3 * 256 + 128 + 2 * 256)
#define F_SMEM_BYTES (F_SMEM_FLOATS * 4)

struct FArgs {
    const float* w1;
    const float* b1;
    const float* w2;
    const float* b2;
    const float* gamma;
    const float* beta;
};

__global__ void __launch_bounds__(512, 1)
ffn_kernel(FArgs args, int M, const float* __restrict__ in1,
           float* __restrict__ out, int out_cvt) {
    extern __shared__ float sm[];
    float* xs  = sm;                       // 64 x 256, stride 260
    float* hb  = xs + 64 * F_XSTR;         // 64 x 128, stride 132
    float* Bst = hb + 64 * F_HSTR;         // weight staging, 2 x F_B2ST
    float* b2s = Bst + 2 * F_B2ST;
    float* gs  = b2s + 256;
    float* bt  = gs + 256;
    float* b1c = bt + 256;
    float* lnS = b1c + 128;
    float* lnQ = lnS + 256;

    int tid = threadIdx.x;
    int bm = blockIdx.x * 64;

    if (tid < 256) {
        b2s[tid] = __ldg(args.b2 + tid);
        gs[tid]  = __ldg(args.gamma + tid);
        bt[tid]  = __ldg(args.beta + tid);
    }
#pragma unroll
    for (int i = 0; i < 8; i++) {
        int idx = tid + i * 512;
        int r = idx >> 6, cv = (idx & 63) << 2;
        int row = bm + r;
        float4 v = make_float4(0.f, 0.f, 0.f, 0.f);
        if (row < M) v = *(const float4*)(in1 + (size_t)row * H + cv);
        *(float4*)(xs + r * F_XSTR + cv) = v;
    }

    uint32_t bst_base = (uint32_t)__cvta_generic_to_shared(Bst);
    int warp = tid >> 5, lane = tid & 31, g = lane >> 2, t = lane & 3;
    int wm = (warp >> 2) * 16;
    int wN = warp & 3;
    int wn1 = wN * 32;     // stage1 warp N-offset (128 cols)
    int wn2 = wN * 64;     // stage2 warp N-offset (256 cols)

    float acc2[8][4];
#pragma unroll
    for (int nf = 0; nf < 8; nf++)
#pragma unroll
        for (int i = 0; i < 4; i++) acc2[nf][i] = 0.f;

    __syncthreads();

    for (int c = 0; c < 8; c++) {
        if (tid < 128) b1c[tid] = __ldg(args.b1 + c * 128 + tid);

        float acc1[4][4];
#pragma unroll
        for (int nf = 0; nf < 4; nf++)
#pragma unroll
            for (int i = 0; i < 4; i++) acc1[nf][i] = 0.f;

        const float* W1 = args.w1 + c * 128;
        auto issue1 = [&](int kt, int buf) {
            int kk = kt * 32;
#pragma unroll
            for (int i = 0; i < 2; i++) {
                int idx = tid + i * 512;
                int r = idx >> 5, nv = (idx & 31) << 2;
                uint32_t dst = bst_base + (uint32_t)((buf * F_B1ST + r * F_B1STR + nv) * 4);
                const float* src = W1 + (size_t)(kk + r) * FH + nv;
                asm volatile("cp.async.cg.shared.global [%0], [%1], 16;\n"
                             :: "r"(dst), "l"(src));
            }
            asm volatile("cp.async.commit_group;\n");
        };

        issue1(0, 0);
        for (int kt = 0; kt < 8; kt++) {
            if (kt + 1 < 8) {
                issue1(kt + 1, (kt + 1) & 1);
                asm volatile("cp.async.wait_group 1;\n");
            } else {
                asm volatile("cp.async.wait_group 0;\n");
            }
            __syncthreads();
            const float* Bb = Bst + (kt & 1) * F_B1ST;
            int kk = kt * 32;
#pragma unroll
            for (int ks = 0; ks < 4; ks++) {
                int kg = kk + ks * 8;
                int kl = ks * 8;
                uint32_t a[4];
                a[0] = __float_as_uint(xs[(wm + g) * F_XSTR + kg + t]);
                a[1] = __float_as_uint(xs[(wm + 8 + g) * F_XSTR + kg + t]);
                a[2] = __float_as_uint(xs[(wm + g) * F_XSTR + kg + t + 4]);
                a[3] = __float_as_uint(xs[(wm + 8 + g) * F_XSTR + kg + t + 4]);
#pragma unroll
                for (int nf = 0; nf < 4; nf++) {
                    uint32_t b[2];
                    b[0] = __float_as_uint(Bb[(kl + t) * F_B1STR + wn1 + nf * 8 + g]);
                    b[1] = __float_as_uint(Bb[(kl + t + 4) * F_B1STR + wn1 + nf * 8 + g]);
                    mma_tf32(acc1[nf], a, b);
                }
            }
            __syncthreads();
        }

        // h = tf32(gelu(acc1 + b1)) -> hb
#pragma unroll
        for (int nf = 0; nf < 4; nf++) {
            int col = wn1 + nf * 8 + 2 * t;
            float h0 = f2tf32f(gelu_exact(acc1[nf][0] + b1c[col]));
            float h1 = f2tf32f(gelu_exact(acc1[nf][1] + b1c[col + 1]));
            float h2 = f2tf32f(gelu_exact(acc1[nf][2] + b1c[col]));
            float h3 = f2tf32f(gelu_exact(acc1[nf][3] + b1c[col + 1]));
            *(float2*)(hb + (wm + g) * F_HSTR + col)     = make_float2(h0, h1);
            *(float2*)(hb + (wm + 8 + g) * F_HSTR + col) = make_float2(h2, h3);
        }
        __syncthreads();

        const float* W2 = args.w2 + (size_t)c * 128 * H;
        auto issue2 = [&](int kt, int buf) {
            int kk = kt * 32;
#pragma unroll
            for (int i = 0; i < 4; i++) {
                int idx = tid + i * 512;
                int r = idx >> 6, nv = (idx & 63) << 2;
                uint32_t dst = bst_base + (uint32_t)((buf * F_B2ST + r * F_B2STR + nv) * 4);
                const float* src = W2 + (size_t)(kk + r) * H + nv;
                asm volatile("cp.async.cg.shared.global [%0], [%1], 16;\n"
                             :: "r"(dst), "l"(src));
            }
            asm volatile("cp.async.commit_group;\n");
        };

        issue2(0, 0);
        for (int kt = 0; kt < 4; kt++) {
            if (kt + 1 < 4) {
                issue2(kt + 1, (kt + 1) & 1);
                asm volatile("cp.async.wait_group 1;\n");
            } else {
                asm volatile("cp.async.wait_group 0;\n");
            }
            __syncthreads();
            const float* Bb = Bst + (kt & 1) * F_B2ST;
            int kk = kt * 32;
#pragma unroll
            for (int ks = 0; ks < 4; ks++) {
                int kg = kk + ks * 8;
                int kl = ks * 8;
                uint32_t a[4];
                a[0] = __float_as_uint(hb[(wm + g) * F_HSTR + kg + t]);
                a[1] = __float_as_uint(hb[(wm + 8 + g) * F_HSTR + kg + t]);
                a[2] = __float_as_uint(hb[(wm + g) * F_HSTR + kg + t + 4]);
                a[3] = __float_as_uint(hb[(wm + 8 + g) * F_HSTR + kg + t + 4]);
#pragma unroll
                for (int nf = 0; nf < 8; nf++) {
                    uint32_t b[2];
                    b[0] = __float_as_uint(Bb[(kl + t) * F_B2STR + wn2 + nf * 8 + g]);
                    b[1] = __float_as_uint(Bb[(kl + t + 4) * F_B2STR + wn2 + nf * 8 + g]);
                    mma_tf32(acc2[nf], a, b);
                }
            }
            __syncthreads();
        }
    }

    // LN2 epilogue
    int row0 = wm + g, row1 = wm + 8 + g;
    float s0 = 0.f, q0 = 0.f, s1 = 0.f, q1 = 0.f;
#pragma unroll
    for (int nf = 0; nf < 8; nf++) {
        int col = wn2 + nf * 8 + 2 * t;
        float t0 = xs[row0 * F_XSTR + col]     + acc2[nf][0] + b2s[col];
        float t1 = xs[row0 * F_XSTR + col + 1] + acc2[nf][1] + b2s[col + 1];
        float t2 = xs[row1 * F_XSTR + col]     + acc2[nf][2] + b2s[col];
        float t3 = xs[row1 * F_XSTR + col + 1] + acc2[nf][3] + b2s[col + 1];
        acc2[nf][0] = t0; acc2[nf][1] = t1; acc2[nf][2] = t2; acc2[nf][3] = t3;
        s0 += t0 + t1; q0 += t0 * t0 + t1 * t1;
        s1 += t2 + t3; q1 += t2 * t2 + t3 * t3;
    }
#pragma unroll
    for (int o = 1; o <= 2; o <<= 1) {
        s0 += __shfl_xor_sync(0xffffffffu, s0, o);
        q0 += __shfl_xor_sync(0xffffffffu, q0, o);
        s1 += __shfl_xor_sync(0xffffffffu, s1, o);
        q1 += __shfl_xor_sync(0xffffffffu, q1, o);
    }
    if (t == 0) {
        lnS[row0 * 4 + wN] = s0; lnQ[row0 * 4 + wN] = q0;
        lnS[row1 * 4 + wN] = s1; lnQ[row1 * 4 + wN] = q1;
    }
    __syncthreads();
    float S0 = lnS[row0 * 4] + lnS[row0 * 4 + 1] + lnS[row0 * 4 + 2] + lnS[row0 * 4 + 3];
    float Q0 = lnQ[row0 * 4] + lnQ[row0 * 4 + 1] + lnQ[row0 * 4 + 2] + lnQ[row0 * 4 + 3];
    float S1 = lnS[row1 * 4] + lnS[row1 * 4 + 1] + lnS[row1 * 4 + 2] + lnS[row1 * 4 + 3];
    float Q1 = lnQ[row1 * 4] + lnQ[row1 * 4 + 1] + lnQ[row1 * 4 + 2] + lnQ[row1 * 4 + 3];
    float m0 = S0 * (1.f / H), v0 = Q0 * (1.f / H) - m0 * m0, r0 = rsqrtf(v0 + 1e-5f);
    float m1 = S1 * (1.f / H), v1 = Q1 * (1.f / H) - m1 * m1, r1 = rsqrtf(v1 + 1e-5f);
    bool ok0 = (bm + row0) < M, ok1 = (bm + row1) < M;
#pragma unroll
    for (int nf = 0; nf < 8; nf++) {
        int col = wn2 + nf * 8 + 2 * t;
        float o0 = (acc2[nf][0] - m0) * r0 * gs[col]     + bt[col];
        float o1 = (acc2[nf][1] - m0) * r0 * gs[col + 1] + bt[col + 1];
        float o2 = (acc2[nf][2] - m1) * r1 * gs[col]     + bt[col];
        float o3 = (acc2[nf][3] - m1) * r1 * gs[col + 1] + bt[col + 1];
        if (out_cvt) {
            o0 = f2tf32f(o0); o1 = f2tf32f(o1);
            o2 = f2tf32f(o2); o3 = f2tf32f(o3);
        }
        if (ok0) *(float2*)(out + (size_t)(bm + row0) * H + col) = make_float2(o0, o1);
        if (ok1) *(float2*)(out + (size_t)(bm + row1) * H + col) = make_float2(o2, o3);
    }
}

// ---------------- host orchestration ----------------

struct Net {
    const float *b_self, *b_khop, *b_fuse, *b_ff1, *b_ff2;
    const float *ln1g, *ln1b, *ln2g, *ln2b;
    float* wbuf;
    float *pz[4], *pout1;
};

static void run_core(const Net& n, int l, int c, int M,
                     const int* rp, const int* ci,
                     const float* xin, const float* fused, float* outp, int cvt_final) {
    size_t lc = (size_t)(l * 2 + c);
    const float* ws = n.wbuf + OFF_WSELF + lc * H * H;
    const float* wf = n.wbuf + OFF_WFUSE + lc * H * H;
    const float* w1 = n.wbuf + OFF_WFF1 + lc * (size_t)H * FH;
    const float* w2 = n.wbuf + OFF_WFF2 + lc * (size_t)FH * H;

    const float* zprev = xin;
    for (int i = 0; i < 4; i++) {
        segsum_kernel<<<(M + 7) / 8, 256>>>(zprev, rp, ci, n.pz[i], M);
        zprev = n.pz[i];
    }

    G1Args ga;
    ga.A[0] = xin; ga.W[0] = ws; ga.Bias[0] = n.b_self + lc * H;
    for (int i = 0; i < 4; i++) {
        ga.A[1 + i] = n.pz[i];
        ga.W[1 + i] = n.wbuf + OFF_WKHOP + (lc * 4 + i) * (size_t)H * H;
        ga.Bias[1 + i] = n.b_khop + (lc * 4 + i) * (size_t)H;
    }
    ga.A[5] = fused; ga.W[5] = wf; ga.Bias[5] = n.b_fuse + lc * H;
    ga.xres = xin;
    ga.gamma = n.ln1g + lc * H;
    ga.beta  = n.ln1b + lc * H;

    int grid = (M + 63) / 64;
    gemm1_ln_kernel<<<grid, 256, G1_SMEM_BYTES>>>(ga, M, n.pout1);

    FArgs fa;
    fa.w1 = w1; fa.b1 = n.b_ff1 + lc * FH;
    fa.w2 = w2; fa.b2 = n.b_ff2 + lc * H;
    fa.gamma = n.ln2g + lc * H;
    fa.beta  = n.ln2b + lc * H;
    ffn_kernel<<<grid, 512, F_SMEM_BYTES>>>(fa, M, n.pout1, outp, cvt_final);
}

static void exclusive_scan(int* cnt, int* rp, int* bsums, int n) {
    int nb = (n + 1023) / 1024;
    scan1_kernel<<<nb, 1024>>>(cnt, rp, bsums, n);
    scan2_kernel<<<1, 1024>>>(bsums, nb);
    scan3_kernel<<<nb, 1024>>>(rp, bsums, cnt, n);
}

extern "C" void kernel_launch(void* const* d_in, const int* in_sizes, int n_in,
                              void* d_out, int out_size) {
    const float* x_in = (const float*)d_in[0];
    const int* feat   = (const int*)d_in[1];
    const int* eig    = (const int*)d_in[2];
    const int* eil    = (const int*)d_in[3];
    const float* rel  = (const float*)d_in[4];

    const float* w_self = (const float*)d_in[5];
    const float* w_khop = (const float*)d_in[7];
    const float* w_fuse = (const float*)d_in[9];
    const float* w_ff1  = (const float*)d_in[11];
    const float* w_ff2  = (const float*)d_in[13];

    Net n;
    n.b_self = (const float*)d_in[6];
    n.b_khop = (const float*)d_in[8];
    n.b_fuse = (const float*)d_in[10];
    n.b_ff1  = (const float*)d_in[12];
    n.b_ff2  = (const float*)d_in[14];
    n.ln1g   = (const float*)d_in[15]; n.ln1b = (const float*)d_in[16];
    n.ln2g   = (const float*)d_in[17]; n.ln2b = (const float*)d_in[18];

    cudaFuncSetAttribute(gemm1_ln_kernel,
                         cudaFuncAttributeMaxDynamicSharedMemorySize, G1_SMEM_BYTES);
    cudaFuncSetAttribute(ffn_kernel,
                         cudaFuncAttributeMaxDynamicSharedMemorySize, F_SMEM_BYTES);

    float *px0, *plg0, *pfn, *pfe, *pzbase, *pout1, *pwbuf;
    int *rp_nd, *ci_nd, *rp_fn, *ci_fn, *rp_lg, *ci_lg, *pcnt, *pcur, *pbs;
    cudaGetSymbolAddress((void**)&px0,   g_x);
    cudaGetSymbolAddress((void**)&plg0,  g_lg);
    cudaGetSymbolAddress((void**)&pfn,   g_fn);
    cudaGetSymbolAddress((void**)&pfe,   g_fe);
    cudaGetSymbolAddress((void**)&pzbase,g_z);
    cudaGetSymbolAddress((void**)&pout1, g_out1);
    cudaGetSymbolAddress((void**)&pwbuf, g_wbuf);
    cudaGetSymbolAddress((void**)&rp_nd, g_rp_nd);
    cudaGetSymbolAddress((void**)&ci_nd, g_ci_nd);
    cudaGetSymbolAddress((void**)&rp_fn, g_rp_fn);
    cudaGetSymbolAddress((void**)&ci_fn, g_ci_fn);
    cudaGetSymbolAddress((void**)&rp_lg, g_rp_lg);
    cudaGetSymbolAddress((void**)&ci_lg, g_ci_lg);
    cudaGetSymbolAddress((void**)&pcnt,  g_cnt);
    cudaGetSymbolAddress((void**)&pcur,  g_cur);
    cudaGetSymbolAddress((void**)&pbs,   g_bs);

    n.wbuf = pwbuf;
    float* px[2]  = {px0,  px0  + (size_t)NNODE * H};
    float* plg[2] = {plg0, plg0 + (size_t)NEDGE * H};
    for (int i = 0; i < 4; i++) n.pz[i] = pzbase + (size_t)i * NEDGE * H;
    n.pout1 = pout1;

    const int* src_g = eig;  const int* dst_g = eig + NEDGE;
    const int* src_l = eil;  const int* dst_l = eil + NLG;

    // --- pre-round weights (tf32 RNA) ---
    auto cvt = [&](const float* src, float* dst, size_t nel) {
        int n4 = (int)(nel / 4);
        cvt_kernel<<<(n4 + 255) / 256, 256>>>(src, dst, n4);
    };
    cvt(w_self, pwbuf + OFF_WSELF, 4 * H * H);
    cvt(w_khop, pwbuf + OFF_WKHOP, 16 * H * H);
    cvt(w_fuse, pwbuf + OFF_WFUSE, 4 * H * H);
    cvt(w_ff1,  pwbuf + OFF_WFF1,  4 * (size_t)H * FH);
    cvt(w_ff2,  pwbuf + OFF_WFF2,  4 * (size_t)FH * H);

    // --- init states (tf32-rounded) ---
    cvt(x_in, px[0], (size_t)NNODE * H);
    embed_kernel<<<NEDGE * 64 / 256, 256>>>(rel, feat, plg[0]);

    // --- build CSRs ---
    cudaMemsetAsync(pcnt, 0, NNODE * sizeof(int), 0);
    hist_kernel<<<(NEDGE + 255) / 256, 256>>>(dst_g, pcnt, NEDGE);
    exclusive_scan(pcnt, rp_nd, pbs, NNODE);
    cudaMemcpyAsync(pcur, rp_nd, NNODE * sizeof(int), cudaMemcpyDeviceToDevice, 0);
    fill_kernel<<<(NEDGE + 255) / 256, 256>>>(dst_g, src_g, pcur, ci_nd, NEDGE);

    cudaMemsetAsync(pcnt, 0, NNODE * sizeof(int), 0);
    hist_kernel<<<(NEDGE + 255) / 256, 256>>>(src_g, pcnt, NEDGE);
    hist_kernel<<<(NEDGE + 255) / 256, 256>>>(dst_g, pcnt, NEDGE);
    exclusive_scan(pcnt, rp_fn, pbs, NNODE);
    cudaMemcpyAsync(pcur, rp_fn, NNODE * sizeof(int), cudaMemcpyDeviceToDevice, 0);
    fill_kernel<<<(NEDGE + 255) / 256, 256>>>(src_g, nullptr, pcur, ci_fn, NEDGE);
    fill_kernel<<<(NEDGE + 255) / 256, 256>>>(dst_g, nullptr, pcur, ci_fn, NEDGE);

    cudaMemsetAsync(pcnt, 0, NEDGE * sizeof(int), 0);
    hist_kernel<<<(NLG + 255) / 256, 256>>>(dst_l, pcnt, NLG);
    exclusive_scan(pcnt, rp_lg, pbs, NEDGE);
    cudaMemcpyAsync(pcur, rp_lg, NEDGE * sizeof(int), cudaMemcpyDeviceToDevice, 0);
    fill_kernel<<<(NLG + 255) / 256, 256>>>(dst_l, src_l, pcur, ci_lg, NLG);

    // --- layers ---
    for (int l = 0; l < 2; l++) {
        float* xcur  = px[l & 1];
        float* lgcur = plg[l & 1];
        int last = (l == 1);
        float* xout  = last ? (float*)d_out : px[(l + 1) & 1];
        float* lgout = last ? (float*)d_out + (size_t)NNODE * H : plg[(l + 1) & 1];

        segsum_kernel<<<(NNODE + 7) / 8, 256>>>(lgcur, rp_fn, ci_fn, pfn, NNODE);
        gather2_kernel<<<NEDGE * 64 / 256, 256>>>(xcur, src_g, dst_g, pfe, NEDGE);

        run_core(n, l, 0, NNODE, rp_nd, ci_nd, xcur, pfn, xout, !last);
        run_core(n, l, 1, NEDGE, rp_lg, ci_lg, lgcur, pfe, lgout, !last);
    }
    (void)in_sizes; (void)n_in; (void)out_size;
}

// round 6
// speedup vs baseline: 1.1260x; 1.1260x over previous
#include <cuda_runtime.h>
#include <cstdint>
#include <math.h>

#define H       256
#define FH      1024
#define NNODE   20000
#define NEDGE   160000
#define NLG     640000

// ---------------- scratch (static device memory; no allocations) ----------------
__device__ float g_x[2][(size_t)NNODE * H];
__device__ float g_lg[2][(size_t)NEDGE * H];
__device__ float g_fn[(size_t)NNODE * H];
__device__ float g_fe[(size_t)NEDGE * H];
__device__ float g_z[4][(size_t)NEDGE * H];    // edge-core khop scratch
__device__ float g_zn[4][(size_t)NNODE * H];   // node-core khop scratch
__device__ float g_out1[(size_t)NEDGE * H];

// packed (tf32-rounded, fragment-order) weights
#define OFF_WSELF 0
#define OFF_WKHOP (OFF_WSELF + 4 * H * H)
#define OFF_WFUSE (OFF_WKHOP + 16 * H * H)
#define OFF_WFF1  (OFF_WFUSE + 4 * H * H)
#define OFF_WFF2  (OFF_WFF1 + 4 * H * FH)
#define WBUF_TOT  (OFF_WFF2 + 4 * FH * H)
__device__ float g_wbuf[WBUF_TOT];

// CSR structures
__device__ int g_rp_nd[NNODE + 1];
__device__ int g_ci_nd[NEDGE];
__device__ int g_rp_fn[NNODE + 1];
__device__ int g_ci_fn[2 * NEDGE];
__device__ int g_rp_lg[NEDGE + 1];
__device__ int g_ci_lg[NLG];
__device__ int g_cnt[NEDGE];
__device__ int g_cur[NEDGE];
__device__ int g_bs[1024];

__device__ __forceinline__ float gelu_exact(float v) {
    return 0.5f * v * (1.0f + erff(v * 0.70710678118654752f));
}

__device__ __forceinline__ float f2tf32f(float f) {
    uint32_t r;
    asm("cvt.rna.tf32.f32 %0, %1;" : "=r"(r) : "f"(f));
    return __uint_as_float(r);
}

__device__ __forceinline__ void mma_tf32(float* c, const uint32_t* a, const uint32_t* b) {
    asm volatile(
        "mma.sync.aligned.m16n8k8.row.col.f32.tf32.tf32.f32 "
        "{%0,%1,%2,%3}, {%4,%5,%6,%7}, {%8,%9}, {%0,%1,%2,%3};"
        : "+f"(c[0]), "+f"(c[1]), "+f"(c[2]), "+f"(c[3])
        : "r"(a[0]), "r"(a[1]), "r"(a[2]), "r"(a[3]), "r"(b[0]), "r"(b[1]));
}

// ---------------- CSR build kernels ----------------

__global__ void hist_kernel(const int* __restrict__ key, int* cnt, int n) {
    int i = blockIdx.x * 256 + threadIdx.x;
    if (i < n) atomicAdd(&cnt[__ldg(key + i)], 1);
}

__global__ void scan1_kernel(const int* __restrict__ in, int* __restrict__ out,
                             int* __restrict__ bsums, int n) {
    __shared__ int sh[1024];
    int i = blockIdx.x * 1024 + threadIdx.x;
    int v = (i < n) ? in[i] : 0;
    sh[threadIdx.x] = v;
    __syncthreads();
#pragma unroll
    for (int o = 1; o < 1024; o <<= 1) {
        int t = (threadIdx.x >= o) ? sh[threadIdx.x - o] : 0;
        __syncthreads();
        sh[threadIdx.x] += t;
        __syncthreads();
    }
    if (i < n) out[i] = sh[threadIdx.x] - v;     // exclusive
    if (threadIdx.x == 1023) bsums[blockIdx.x] = sh[1023];
}

__global__ void scan2_kernel(int* bsums, int nb) {
    __shared__ int sh[1024];
    int v = (threadIdx.x < nb) ? bsums[threadIdx.x] : 0;
    sh[threadIdx.x] = v;
    __syncthreads();
#pragma unroll
    for (int o = 1; o < 1024; o <<= 1) {
        int t = (threadIdx.x >= o) ? sh[threadIdx.x - o] : 0;
        __syncthreads();
        sh[threadIdx.x] += t;
        __syncthreads();
    }
    if (threadIdx.x < nb) bsums[threadIdx.x] = sh[threadIdx.x] - v;  // exclusive
}

__global__ void scan3_kernel(int* __restrict__ out, const int* __restrict__ bsums,
                             const int* __restrict__ cnt, int n) {
    int i = blockIdx.x * 1024 + threadIdx.x;
    if (i < n) {
        int v = out[i] + bsums[i >> 10];
        out[i] = v;
        if (i == n - 1) out[n] = v + cnt[i];
    }
}

__global__ void fill_kernel(const int* __restrict__ key, const int* __restrict__ val,
                            int* cursor, int* __restrict__ ci, int n) {
    int i = blockIdx.x * 256 + threadIdx.x;
    if (i >= n) return;
    int pos = atomicAdd(&cursor[__ldg(key + i)], 1);
    ci[pos] = val ? __ldg(val + i) : i;
}

// ---------------- weight pack kernels (tf32 round + fragment permutation) ----------------
// Layout per 32x256 k-tile (gemm1/ff2 shapes): [ks(4)][wN][nf2][lane(32)] float4
// float4 = { W[k][n], W[k+4][n], W[k][n+8], W[k+4][n+8] },  k = kt*32+ks*8+t, t=lane&3, g=lane>>2

// H x H matrices (w_self / w_khop / w_fuse): out tile = [kt(8)] x 2048 float4
__global__ void pack256_kernel(const float* __restrict__ W, float* __restrict__ out, int nmat) {
    int gid = blockIdx.x * 256 + threadIdx.x;
    if (gid >= nmat * 16384) return;
    int m = gid >> 14, o = gid & 16383;
    int kt = o >> 11, i4 = o & 2047;
    int ks = i4 >> 9, r = i4 & 511;
    int wN = r >> 8, r3 = r & 255;
    int nf2 = r3 >> 5, lane = r3 & 31;
    int t = lane & 3, g = lane >> 2;
    int k = kt * 32 + ks * 8 + t;
    int n = wN * 128 + nf2 * 16 + g;
    const float* Wm = W + (size_t)m * 65536;
    float4 v;
    v.x = f2tf32f(Wm[k * 256 + n]);
    v.y = f2tf32f(Wm[(k + 4) * 256 + n]);
    v.z = f2tf32f(Wm[k * 256 + n + 8]);
    v.w = f2tf32f(Wm[(k + 4) * 256 + n + 8]);
    ((float4*)out)[gid] = v;
}

// w_ff1 [256, 1024]: [c(8)][kt(8)][ks(4)][wN(4)][nf2(2)][lane] float4
__global__ void packff1_kernel(const float* __restrict__ W, float* __restrict__ out, int nmat) {
    int gid = blockIdx.x * 256 + threadIdx.x;
    if (gid >= nmat * 65536) return;
    int m = gid >> 16, o = gid & 65535;
    int c = o >> 13, r = o & 8191;
    int kt = r >> 10, i4 = r & 1023;
    int ks = i4 >> 8, r2 = i4 & 255;
    int wN = r2 >> 6, r3 = r2 & 63;
    int nf2 = r3 >> 5, lane = r3 & 31;
    int t = lane & 3, g = lane >> 2;
    int k = kt * 32 + ks * 8 + t;
    int n = c * 128 + wN * 32 + nf2 * 16 + g;
    const float* Wm = W + (size_t)m * 262144;
    float4 v;
    v.x = f2tf32f(Wm[k * 1024 + n]);
    v.y = f2tf32f(Wm[(k + 4) * 1024 + n]);
    v.z = f2tf32f(Wm[k * 1024 + n + 8]);
    v.w = f2tf32f(Wm[(k + 4) * 1024 + n + 8]);
    ((float4*)out)[gid] = v;
}

// w_ff2 [1024, 256]: [c(8)][kt(4)][ks(4)][wN(4)][nf2(4)][lane] float4
__global__ void packff2_kernel(const float* __restrict__ W, float* __restrict__ out, int nmat) {
    int gid = blockIdx.x * 256 + threadIdx.x;
    if (gid >= nmat * 65536) return;
    int m = gid >> 16, o = gid & 65535;
    int c = o >> 13, r = o & 8191;
    int kt = r >> 11, i4 = r & 2047;
    int ks = i4 >> 9, r2 = i4 & 511;
    int wN = r2 >> 7, r3 = r2 & 127;
    int nf2 = r3 >> 5, lane = r3 & 31;
    int t = lane & 3, g = lane >> 2;
    int k = c * 128 + kt * 32 + ks * 8 + t;
    int n = wN * 64 + nf2 * 16 + g;
    const float* Wm = W + (size_t)m * 262144;
    float4 v;
    v.x = f2tf32f(Wm[k * 256 + n]);
    v.y = f2tf32f(Wm[(k + 4) * 256 + n]);
    v.z = f2tf32f(Wm[k * 256 + n + 8]);
    v.w = f2tf32f(Wm[(k + 4) * 256 + n + 8]);
    ((float4*)out)[gid] = v;
}

// ---------------- small kernels ----------------

__global__ void cvt_kernel(const float* __restrict__ in, float* __restrict__ out, int n4) {
    int i = blockIdx.x * 256 + threadIdx.x;
    if (i >= n4) return;
    float4 v = ((const float4*)in)[i];
    v.x = f2tf32f(v.x); v.y = f2tf32f(v.y); v.z = f2tf32f(v.z); v.w = f2tf32f(v.w);
    ((float4*)out)[i] = v;
}

__global__ void embed_kernel(const float* __restrict__ rel, const int* __restrict__ feat,
                             float* __restrict__ out) {
    int gid = blockIdx.x * blockDim.x + threadIdx.x;
    int e = gid >> 6;
    if (e >= NEDGE) return;
    int c = (gid & 63) << 2;
    int r = __ldg(feat + e);
    float4 v = *(const float4*)(rel + (size_t)r * H + c);
    v.x = f2tf32f(v.x); v.y = f2tf32f(v.y); v.z = f2tf32f(v.z); v.w = f2tf32f(v.w);
    *(float4*)(out + (size_t)e * H + c) = v;
}

__global__ void gather2_kernel(const float* __restrict__ x, const int* __restrict__ s,
                               const int* __restrict__ d, float* __restrict__ out, int n) {
    int gid = blockIdx.x * blockDim.x + threadIdx.x;
    int e = gid >> 6;
    if (e >= n) return;
    int c = (gid & 63) << 2;
    int si = __ldg(s + e), di = __ldg(d + e);
    float4 a = *(const float4*)(x + (size_t)si * H + c);
    float4 b = *(const float4*)(x + (size_t)di * H + c);
    a.x = f2tf32f(a.x + b.x); a.y = f2tf32f(a.y + b.y);
    a.z = f2tf32f(a.z + b.z); a.w = f2tf32f(a.w + b.w);
    *(float4*)(out + (size_t)e * H + c) = a;
}

// CSR gather segment-sum (2-way unrolled): out[r] = tf32( sum rows[ci[j]] )
__global__ void segsum_kernel(const float* __restrict__ rows, const int* __restrict__ rp,
                              const int* __restrict__ ci, float* __restrict__ out, int nseg) {
    int row = blockIdx.x * 8 + (threadIdx.x >> 5);
    if (row >= nseg) return;
    int lane = threadIdx.x & 31;
    int beg = __ldg(rp + row), end = __ldg(rp + row + 1);
    float a[8] = {0.f, 0.f, 0.f, 0.f, 0.f, 0.f, 0.f, 0.f};
    float b[8] = {0.f, 0.f, 0.f, 0.f, 0.f, 0.f, 0.f, 0.f};
    int j = beg;
    for (; j + 1 < end; j += 2) {
        const float* p0 = rows + (size_t)__ldg(ci + j) * H + lane * 8;
        const float* p1 = rows + (size_t)__ldg(ci + j + 1) * H + lane * 8;
        float4 u0 = ((const float4*)p0)[0], u1 = ((const float4*)p0)[1];
        float4 w0 = ((const float4*)p1)[0], w1 = ((const float4*)p1)[1];
        a[0] += u0.x; a[1] += u0.y; a[2] += u0.z; a[3] += u0.w;
        a[4] += u1.x; a[5] += u1.y; a[6] += u1.z; a[7] += u1.w;
        b[0] += w0.x; b[1] += w0.y; b[2] += w0.z; b[3] += w0.w;
        b[4] += w1.x; b[5] += w1.y; b[6] += w1.z; b[7] += w1.w;
    }
    if (j < end) {
        const float* p0 = rows + (size_t)__ldg(ci + j) * H + lane * 8;
        float4 u0 = ((const float4*)p0)[0], u1 = ((const float4*)p0)[1];
        a[0] += u0.x; a[1] += u0.y; a[2] += u0.z; a[3] += u0.w;
        a[4] += u1.x; a[5] += u1.y; a[6] += u1.z; a[7] += u1.w;
    }
#pragma unroll
    for (int i = 0; i < 8; i++) a[i] = f2tf32f(a[i] + b[i]);
    float* po = out + (size_t)row * H + lane * 8;
    ((float4*)po)[0] = make_float4(a[0], a[1], a[2], a[3]);
    ((float4*)po)[1] = make_float4(a[4], a[5], a[6], a[7]);
}

// hop1 of layer-0 edge core: gather rel[feat[ci[j]]] (rel is L2-resident, 128 KB)
__global__ void segsum_rel_kernel(const float* __restrict__ rel, const int* __restrict__ feat,
                                  const int* __restrict__ rp, const int* __restrict__ ci,
                                  float* __restrict__ out, int nseg) {
    int row = blockIdx.x * 8 + (threadIdx.x >> 5);
    if (row >= nseg) return;
    int lane = threadIdx.x & 31;
    int beg = __ldg(rp + row), end = __ldg(rp + row + 1);
    float a[8] = {0.f, 0.f, 0.f, 0.f, 0.f, 0.f, 0.f, 0.f};
    for (int j = beg; j < end; j++) {
        int r = __ldg(feat + __ldg(ci + j));
        const float* p = rel + (size_t)r * H + lane * 8;
        float4 u0 = ((const float4*)p)[0], u1 = ((const float4*)p)[1];
        a[0] += f2tf32f(u0.x); a[1] += f2tf32f(u0.y);
        a[2] += f2tf32f(u0.z); a[3] += f2tf32f(u0.w);
        a[4] += f2tf32f(u1.x); a[5] += f2tf32f(u1.y);
        a[6] += f2tf32f(u1.z); a[7] += f2tf32f(u1.w);
    }
#pragma unroll
    for (int i = 0; i < 8; i++) a[i] = f2tf32f(a[i]);
    float* po = out + (size_t)row * H + lane * 8;
    ((float4*)po)[0] = make_float4(a[0], a[1], a[2], a[3]);
    ((float4*)po)[1] = make_float4(a[4], a[5], a[6], a[7]);
}

// ================= GEMM1 + LN1 fused =================
// out1 = tf32( LN( xres + gelu( sum_j A_j @ W_j + sum_j bias_j ) ) )
// BM=64, BN=256, K = 6 x 256, 256 threads. W packed in fragment order.

#define G_ASTR 36
#define G_AST (64 * G_ASTR)       // 2304
#define G_BST 8192
#define G1_SMEM_FLOATS (2 * G_AST + 2 * G_BST + 3 * 256 + 256)
#define G1_SMEM_BYTES (G1_SMEM_FLOATS * 4)

struct G1Args {
    const float* A[6];
    const float* W[6];       // packed
    const float* Bias[6];
    const float* xres;
    const float* gamma;
    const float* beta;
};

__global__ void __launch_bounds__(256, 2)
gemm1_ln_kernel(G1Args args, int M, float* __restrict__ out) {
    extern __shared__ float sm[];
    float* As = sm;
    float* Bs = sm + 2 * G_AST;
    float* bias_s = Bs + 2 * G_BST;
    float* gs = bias_s + 256;
    float* bt = gs + 256;
    float* lnS = bt + 256;
    float* lnQ = lnS + 128;
    float* xs = sm;                 // alias; reused after mainloop, stride 264

    int tid = threadIdx.x;
    int bm = blockIdx.x * 64;

    {
        float b = 0.f;
#pragma unroll
        for (int j = 0; j < 6; j++) b += __ldg(args.Bias[j] + tid);
        bias_s[tid] = b;
        gs[tid] = __ldg(args.gamma + tid);
        bt[tid] = __ldg(args.beta + tid);
    }

    uint32_t a_base = (uint32_t)__cvta_generic_to_shared(As);
    uint32_t b_base = (uint32_t)__cvta_generic_to_shared(Bs);

    int warp = tid >> 5, lane = tid & 31, g = lane >> 2, t = lane & 3;
    int wm = (warp >> 1) * 16;
    int wN = warp & 1;
    int wn = wN * 128;

    float acc[16][4];
#pragma unroll
    for (int nf = 0; nf < 16; nf++)
#pragma unroll
        for (int i = 0; i < 4; i++) acc[nf][i] = 0.f;

    auto issue = [&](int tt, int buf) {
        int j = tt >> 3;
        int kk = (tt & 7) * 32;
        const float* A = args.A[j];
        const float4* Wp = (const float4*)args.W[j] + (size_t)(tt & 7) * 2048;
#pragma unroll
        for (int i = 0; i < 2; i++) {
            int idx = tid + i * 256;
            int r = idx >> 3, kv = (idx & 7) << 2;
            int row = bm + r;
            uint32_t dst = a_base + (uint32_t)((buf * G_AST + r * G_ASTR + kv) * 4);
            const float* src = A + (size_t)row * H + kk + kv;
            int sz = (row < M) ? 16 : 0;
            asm volatile("cp.async.cg.shared.global [%0], [%1], 16, %2;\n"
                         :: "r"(dst), "l"(src), "r"(sz));
        }
#pragma unroll
        for (int i = 0; i < 8; i++) {
            int idx = tid + i * 256;
            uint32_t dst = b_base + (uint32_t)((buf * G_BST + idx * 4) * 4);
            asm volatile("cp.async.cg.shared.global [%0], [%1], 16;\n"
                         :: "r"(dst), "l"(Wp + idx));
        }
        asm volatile("cp.async.commit_group;\n");
    };

    issue(0, 0);
    for (int tt = 0; tt < 48; tt++) {
        if (tt + 1 < 48) {
            issue(tt + 1, (tt + 1) & 1);
            asm volatile("cp.async.wait_group 1;\n");
        } else {
            asm volatile("cp.async.wait_group 0;\n");
        }
        __syncthreads();
        const float* Ab = As + (tt & 1) * G_AST;
        const float4* Bb4 = (const float4*)(Bs + (tt & 1) * G_BST) + wN * 256 + lane;
#pragma unroll
        for (int ks = 0; ks < 4; ks++) {
            int k0 = ks * 8;
            uint32_t a[4];
            a[0] = __float_as_uint(Ab[(wm + g) * G_ASTR + k0 + t]);
            a[1] = __float_as_uint(Ab[(wm + 8 + g) * G_ASTR + k0 + t]);
            a[2] = __float_as_uint(Ab[(wm + g) * G_ASTR + k0 + t + 4]);
            a[3] = __float_as_uint(Ab[(wm + 8 + g) * G_ASTR + k0 + t + 4]);
#pragma unroll
            for (int nf2 = 0; nf2 < 8; nf2++) {
                float4 bv = Bb4[ks * 512 + nf2 * 32];
                uint32_t b0[2] = {__float_as_uint(bv.x), __float_as_uint(bv.y)};
                mma_tf32(acc[2 * nf2], a, b0);
                uint32_t b1[2] = {__float_as_uint(bv.z), __float_as_uint(bv.w)};
                mma_tf32(acc[2 * nf2 + 1], a, b1);
            }
        }
        __syncthreads();
    }

    // cooperative residual tile load into xs (stride 264)
#pragma unroll
    for (int i = 0; i < 16; i++) {
        int idx = tid + i * 256;
        int r = idx >> 6, cv = (idx & 63) << 2;
        int row = bm + r;
        float4 v = make_float4(0.f, 0.f, 0.f, 0.f);
        if (row < M) v = *(const float4*)(args.xres + (size_t)row * H + cv);
        *(float4*)(xs + r * 264 + cv) = v;
    }
    __syncthreads();

    int row0 = wm + g, row1 = wm + 8 + g;
    float s0 = 0.f, q0 = 0.f, s1 = 0.f, q1 = 0.f;
#pragma unroll
    for (int nf = 0; nf < 16; nf++) {
        int col = wn + nf * 8 + 2 * t;
        float t0 = xs[row0 * 264 + col]     + gelu_exact(acc[nf][0] + bias_s[col]);
        float t1 = xs[row0 * 264 + col + 1] + gelu_exact(acc[nf][1] + bias_s[col + 1]);
        float t2 = xs[row1 * 264 + col]     + gelu_exact(acc[nf][2] + bias_s[col]);
        float t3 = xs[row1 * 264 + col + 1] + gelu_exact(acc[nf][3] + bias_s[col + 1]);
        acc[nf][0] = t0; acc[nf][1] = t1; acc[nf][2] = t2; acc[nf][3] = t3;
        s0 += t0 + t1; q0 += t0 * t0 + t1 * t1;
        s1 += t2 + t3; q1 += t2 * t2 + t3 * t3;
    }
#pragma unroll
    for (int o = 1; o <= 2; o <<= 1) {
        s0 += __shfl_xor_sync(0xffffffffu, s0, o);
        q0 += __shfl_xor_sync(0xffffffffu, q0, o);
        s1 += __shfl_xor_sync(0xffffffffu, s1, o);
        q1 += __shfl_xor_sync(0xffffffffu, q1, o);
    }
    if (t == 0) {
        lnS[row0 * 2 + wN] = s0; lnQ[row0 * 2 + wN] = q0;
        lnS[row1 * 2 + wN] = s1; lnQ[row1 * 2 + wN] = q1;
    }
    __syncthreads();
    float S0 = lnS[row0 * 2] + lnS[row0 * 2 + 1];
    float Q0 = lnQ[row0 * 2] + lnQ[row0 * 2 + 1];
    float S1 = lnS[row1 * 2] + lnS[row1 * 2 + 1];
    float Q1 = lnQ[row1 * 2] + lnQ[row1 * 2 + 1];
    float m0 = S0 * (1.f / H), v0 = Q0 * (1.f / H) - m0 * m0, r0 = rsqrtf(v0 + 1e-5f);
    float m1 = S1 * (1.f / H), v1 = Q1 * (1.f / H) - m1 * m1, r1 = rsqrtf(v1 + 1e-5f);
    bool ok0 = (bm + row0) < M, ok1 = (bm + row1) < M;
#pragma unroll
    for (int nf = 0; nf < 16; nf++) {
        int col = wn + nf * 8 + 2 * t;
        float o0 = f2tf32f((acc[nf][0] - m0) * r0 * gs[col]     + bt[col]);
        float o1 = f2tf32f((acc[nf][1] - m0) * r0 * gs[col + 1] + bt[col + 1]);
        float o2 = f2tf32f((acc[nf][2] - m1) * r1 * gs[col]     + bt[col]);
        float o3 = f2tf32f((acc[nf][3] - m1) * r1 * gs[col + 1] + bt[col + 1]);
        if (ok0) *(float2*)(out + (size_t)(bm + row0) * H + col) = make_float2(o0, o1);
        if (ok1) *(float2*)(out + (size_t)(bm + row1) * H + col) = make_float2(o2, o3);
    }
}

// ================= fused FFN + LN2 =================
// out = LN( out1 + gelu(out1 @ w1 + b1) @ w2 + b2 ); packed weights.

#define F_XSTR 260
#define F_HSTR 132
#define F_B1ST 4096
#define F_B2ST 8192
#define F_SMEM_FLOATS (64 * F_XSTR + 64 * F_HSTR + 2 * F_B2ST + 3 * 256 + 128 + 2 * 256)
#define F_SMEM_BYTES (F_SMEM_FLOATS * 4)

struct FArgs {
    const float* w1;    // packed
    const float* b1;
    const float* w2;    // packed
    const float* b2;
    const float* gamma;
    const float* beta;
};

__global__ void __launch_bounds__(512, 1)
ffn_kernel(FArgs args, int M, const float* __restrict__ in1,
           float* __restrict__ out, int out_cvt) {
    extern __shared__ float sm[];
    float* xs  = sm;                       // 64 x 256, stride 260
    float* hb  = xs + 64 * F_XSTR;         // 64 x 128, stride 132
    float* Bst = hb + 64 * F_HSTR;         // weight staging, 2 x F_B2ST
    float* b2s = Bst + 2 * F_B2ST;
    float* gs  = b2s + 256;
    float* bt  = gs + 256;
    float* b1c = bt + 256;
    float* lnS = b1c + 128;
    float* lnQ = lnS + 256;

    int tid = threadIdx.x;
    int bm = blockIdx.x * 64;

    if (tid < 256) {
        b2s[tid] = __ldg(args.b2 + tid);
        gs[tid]  = __ldg(args.gamma + tid);
        bt[tid]  = __ldg(args.beta + tid);
    }
#pragma unroll
    for (int i = 0; i < 8; i++) {
        int idx = tid + i * 512;
        int r = idx >> 6, cv = (idx & 63) << 2;
        int row = bm + r;
        float4 v = make_float4(0.f, 0.f, 0.f, 0.f);
        if (row < M) v = *(const float4*)(in1 + (size_t)row * H + cv);
        *(float4*)(xs + r * F_XSTR + cv) = v;
    }

    uint32_t bst_base = (uint32_t)__cvta_generic_to_shared(Bst);
    int warp = tid >> 5, lane = tid & 31, g = lane >> 2, t = lane & 3;
    int wm = (warp >> 2) * 16;
    int wN = warp & 3;
    int wn1 = wN * 32;
    int wn2 = wN * 64;

    float acc2[8][4];
#pragma unroll
    for (int nf = 0; nf < 8; nf++)
#pragma unroll
        for (int i = 0; i < 4; i++) acc2[nf][i] = 0.f;

    __syncthreads();

    for (int c = 0; c < 8; c++) {
        if (tid < 128) b1c[tid] = __ldg(args.b1 + c * 128 + tid);

        float acc1[4][4];
#pragma unroll
        for (int nf = 0; nf < 4; nf++)
#pragma unroll
            for (int i = 0; i < 4; i++) acc1[nf][i] = 0.f;

        const float4* W1p = (const float4*)args.w1 + (size_t)c * 8192;
        auto issue1 = [&](int kt, int buf) {
#pragma unroll
            for (int i = 0; i < 2; i++) {
                int idx = tid + i * 512;
                uint32_t dst = bst_base + (uint32_t)((buf * F_B1ST + idx * 4) * 4);
                asm volatile("cp.async.cg.shared.global [%0], [%1], 16;\n"
                             :: "r"(dst), "l"(W1p + kt * 1024 + idx));
            }
            asm volatile("cp.async.commit_group;\n");
        };

        issue1(0, 0);
        for (int kt = 0; kt < 8; kt++) {
            if (kt + 1 < 8) {
                issue1(kt + 1, (kt + 1) & 1);
                asm volatile("cp.async.wait_group 1;\n");
            } else {
                asm volatile("cp.async.wait_group 0;\n");
            }
            __syncthreads();
            const float4* Bb4 = (const float4*)(Bst + (kt & 1) * F_B1ST) + wN * 64 + lane;
            int kk = kt * 32;
#pragma unroll
            for (int ks = 0; ks < 4; ks++) {
                int kg = kk + ks * 8;
                uint32_t a[4];
                a[0] = __float_as_uint(xs[(wm + g) * F_XSTR + kg + t]);
                a[1] = __float_as_uint(xs[(wm + 8 + g) * F_XSTR + kg + t]);
                a[2] = __float_as_uint(xs[(wm + g) * F_XSTR + kg + t + 4]);
                a[3] = __float_as_uint(xs[(wm + 8 + g) * F_XSTR + kg + t + 4]);
#pragma unroll
                for (int nf2 = 0; nf2 < 2; nf2++) {
                    float4 bv = Bb4[ks * 256 + nf2 * 32];
                    uint32_t b0[2] = {__float_as_uint(bv.x), __float_as_uint(bv.y)};
                    mma_tf32(acc1[2 * nf2], a, b0);
                    uint32_t b1[2] = {__float_as_uint(bv.z), __float_as_uint(bv.w)};
                    mma_tf32(acc1[2 * nf2 + 1], a, b1);
                }
            }
            __syncthreads();
        }

        // h = tf32(gelu(acc1 + b1)) -> hb
#pragma unroll
        for (int nf = 0; nf < 4; nf++) {
            int col = wn1 + nf * 8 + 2 * t;
            float h0 = f2tf32f(gelu_exact(acc1[nf][0] + b1c[col]));
            float h1 = f2tf32f(gelu_exact(acc1[nf][1] + b1c[col + 1]));
            float h2 = f2tf32f(gelu_exact(acc1[nf][2] + b1c[col]));
            float h3 = f2tf32f(gelu_exact(acc1[nf][3] + b1c[col + 1]));
            *(float2*)(hb + (wm + g) * F_HSTR + col)     = make_float2(h0, h1);
            *(float2*)(hb + (wm + 8 + g) * F_HSTR + col) = make_float2(h2, h3);
        }
        __syncthreads();

        const float4* W2p = (const float4*)args.w2 + (size_t)c * 8192;
        auto issue2 = [&](int kt, int buf) {
#pragma unroll
            for (int i = 0; i < 4; i++) {
                int idx = tid + i * 512;
                uint32_t dst = bst_base + (uint32_t)((buf * F_B2ST + idx * 4) * 4);
                asm volatile("cp.async.cg.shared.global [%0], [%1], 16;\n"
                             :: "r"(dst), "l"(W2p + kt * 2048 + idx));
            }
            asm volatile("cp.async.commit_group;\n");
        };

        issue2(0, 0);
        for (int kt = 0; kt < 4; kt++) {
            if (kt + 1 < 4) {
                issue2(kt + 1, (kt + 1) & 1);
                asm volatile("cp.async.wait_group 1;\n");
            } else {
                asm volatile("cp.async.wait_group 0;\n");
            }
            __syncthreads();
            const float4* Bb4 = (const float4*)(Bst + (kt & 1) * F_B2ST) + wN * 128 + lane;
            int kk = kt * 32;
#pragma unroll
            for (int ks = 0; ks < 4; ks++) {
                int kg = kk + ks * 8;
                uint32_t a[4];
                a[0] = __float_as_uint(hb[(wm + g) * F_HSTR + kg + t]);
                a[1] = __float_as_uint(hb[(wm + 8 + g) * F_HSTR + kg + t]);
                a[2] = __float_as_uint(hb[(wm + g) * F_HSTR + kg + t + 4]);
                a[3] = __float_as_uint(hb[(wm + 8 + g) * F_HSTR + kg + t + 4]);
#pragma unroll
                for (int nf2 = 0; nf2 < 4; nf2++) {
                    float4 bv = Bb4[ks * 512 + nf2 * 32];
                    uint32_t b0[2] = {__float_as_uint(bv.x), __float_as_uint(bv.y)};
                    mma_tf32(acc2[2 * nf2], a, b0);
                    uint32_t b1[2] = {__float_as_uint(bv.z), __float_as_uint(bv.w)};
                    mma_tf32(acc2[2 * nf2 + 1], a, b1);
                }
            }
            __syncthreads();
        }
    }

    // LN2 epilogue
    int row0 = wm + g, row1 = wm + 8 + g;
    float s0 = 0.f, q0 = 0.f, s1 = 0.f, q1 = 0.f;
#pragma unroll
    for (int nf = 0; nf < 8; nf++) {
        int col = wn2 + nf * 8 + 2 * t;
        float t0 = xs[row0 * F_XSTR + col]     + acc2[nf][0] + b2s[col];
        float t1 = xs[row0 * F_XSTR + col + 1] + acc2[nf][1] + b2s[col + 1];
        float t2 = xs[row1 * F_XSTR + col]     + acc2[nf][2] + b2s[col];
        float t3 = xs[row1 * F_XSTR + col + 1] + acc2[nf][3] + b2s[col + 1];
        acc2[nf][0] = t0; acc2[nf][1] = t1; acc2[nf][2] = t2; acc2[nf][3] = t3;
        s0 += t0 + t1; q0 += t0 * t0 + t1 * t1;
        s1 += t2 + t3; q1 += t2 * t2 + t3 * t3;
    }
#pragma unroll
    for (int o = 1; o <= 2; o <<= 1) {
        s0 += __shfl_xor_sync(0xffffffffu, s0, o);
        q0 += __shfl_xor_sync(0xffffffffu, q0, o);
        s1 += __shfl_xor_sync(0xffffffffu, s1, o);
        q1 += __shfl_xor_sync(0xffffffffu, q1, o);
    }
    if (t == 0) {
        lnS[row0 * 4 + wN] = s0; lnQ[row0 * 4 + wN] = q0;
        lnS[row1 * 4 + wN] = s1; lnQ[row1 * 4 + wN] = q1;
    }
    __syncthreads();
    float S0 = lnS[row0 * 4] + lnS[row0 * 4 + 1] + lnS[row0 * 4 + 2] + lnS[row0 * 4 + 3];
    float Q0 = lnQ[row0 * 4] + lnQ[row0 * 4 + 1] + lnQ[row0 * 4 + 2] + lnQ[row0 * 4 + 3];
    float S1 = lnS[row1 * 4] + lnS[row1 * 4 + 1] + lnS[row1 * 4 + 2] + lnS[row1 * 4 + 3];
    float Q1 = lnQ[row1 * 4] + lnQ[row1 * 4 + 1] + lnQ[row1 * 4 + 2] + lnQ[row1 * 4 + 3];
    float m0 = S0 * (1.f / H), v0 = Q0 * (1.f / H) - m0 * m0, r0 = rsqrtf(v0 + 1e-5f);
    float m1 = S1 * (1.f / H), v1 = Q1 * (1.f / H) - m1 * m1, r1 = rsqrtf(v1 + 1e-5f);
    bool ok0 = (bm + row0) < M, ok1 = (bm + row1) < M;
#pragma unroll
    for (int nf = 0; nf < 8; nf++) {
        int col = wn2 + nf * 8 + 2 * t;
        float o0 = (acc2[nf][0] - m0) * r0 * gs[col]     + bt[col];
        float o1 = (acc2[nf][1] - m0) * r0 * gs[col + 1] + bt[col + 1];
        float o2 = (acc2[nf][2] - m1) * r1 * gs[col]     + bt[col];
        float o3 = (acc2[nf][3] - m1) * r1 * gs[col + 1] + bt[col + 1];
        if (out_cvt) {
            o0 = f2tf32f(o0); o1 = f2tf32f(o1);
            o2 = f2tf32f(o2); o3 = f2tf32f(o3);
        }
        if (ok0) *(float2*)(out + (size_t)(bm + row0) * H + col) = make_float2(o0, o1);
        if (ok1) *(float2*)(out + (size_t)(bm + row1) * H + col) = make_float2(o2, o3);
    }
}

// ---------------- host orchestration ----------------

struct Net {
    const float *b_self, *b_khop, *b_fuse, *b_ff1, *b_ff2;
    const float *ln1g, *ln1b, *ln2g, *ln2b;
    float* wbuf;
    float *pout1;
};

static void run_core(const Net& n, int l, int c, int M, float* const* z,
                     const float* xin, const float* fused, float* outp, int cvt_final) {
    size_t lc = (size_t)(l * 2 + c);
    G1Args ga;
    ga.A[0] = xin;
    ga.W[0] = n.wbuf + OFF_WSELF + lc * H * H;
    ga.Bias[0] = n.b_self + lc * H;
    for (int i = 0; i < 4; i++) {
        ga.A[1 + i] = z[i];
        ga.W[1 + i] = n.wbuf + OFF_WKHOP + (lc * 4 + i) * (size_t)H * H;
        ga.Bias[1 + i] = n.b_khop + (lc * 4 + i) * (size_t)H;
    }
    ga.A[5] = fused;
    ga.W[5] = n.wbuf + OFF_WFUSE + lc * H * H;
    ga.Bias[5] = n.b_fuse + lc * H;
    ga.xres = xin;
    ga.gamma = n.ln1g + lc * H;
    ga.beta  = n.ln1b + lc * H;

    int grid = (M + 63) / 64;
    gemm1_ln_kernel<<<grid, 256, G1_SMEM_BYTES>>>(ga, M, n.pout1);

    FArgs fa;
    fa.w1 = n.wbuf + OFF_WFF1 + lc * (size_t)H * FH;
    fa.b1 = n.b_ff1 + lc * FH;
    fa.w2 = n.wbuf + OFF_WFF2 + lc * (size_t)FH * H;
    fa.b2 = n.b_ff2 + lc * H;
    fa.gamma = n.ln2g + lc * H;
    fa.beta  = n.ln2b + lc * H;
    ffn_kernel<<<grid, 512, F_SMEM_BYTES>>>(fa, M, n.pout1, outp, cvt_final);
}

static void exclusive_scan(int* cnt, int* rp, int* bsums, int n) {
    int nb = (n + 1023) / 1024;
    scan1_kernel<<<nb, 1024>>>(cnt, rp, bsums, n);
    scan2_kernel<<<1, 1024>>>(bsums, nb);
    scan3_kernel<<<nb, 1024>>>(rp, bsums, cnt, n);
}

extern "C" void kernel_launch(void* const* d_in, const int* in_sizes, int n_in,
                              void* d_out, int out_size) {
    const float* x_in = (const float*)d_in[0];
    const int* feat   = (const int*)d_in[1];
    const int* eig    = (const int*)d_in[2];
    const int* eil    = (const int*)d_in[3];
    const float* rel  = (const float*)d_in[4];

    const float* w_self = (const float*)d_in[5];
    const float* w_khop = (const float*)d_in[7];
    const float* w_fuse = (const float*)d_in[9];
    const float* w_ff1  = (const float*)d_in[11];
    const float* w_ff2  = (const float*)d_in[13];

    Net n;
    n.b_self = (const float*)d_in[6];
    n.b_khop = (const float*)d_in[8];
    n.b_fuse = (const float*)d_in[10];
    n.b_ff1  = (const float*)d_in[12];
    n.b_ff2  = (const float*)d_in[14];
    n.ln1g   = (const float*)d_in[15]; n.ln1b = (const float*)d_in[16];
    n.ln2g   = (const float*)d_in[17]; n.ln2b = (const float*)d_in[18];

    cudaFuncSetAttribute(gemm1_ln_kernel,
                         cudaFuncAttributeMaxDynamicSharedMemorySize, G1_SMEM_BYTES);
    cudaFuncSetAttribute(ffn_kernel,
                         cudaFuncAttributeMaxDynamicSharedMemorySize, F_SMEM_BYTES);

    float *px0, *plg0, *pfn, *pfe, *pzbase, *pznb, *pout1, *pwbuf;
    int *rp_nd, *ci_nd, *rp_fn, *ci_fn, *rp_lg, *ci_lg, *pcnt, *pcur, *pbs;
    cudaGetSymbolAddress((void**)&px0,   g_x);
    cudaGetSymbolAddress((void**)&plg0,  g_lg);
    cudaGetSymbolAddress((void**)&pfn,   g_fn);
    cudaGetSymbolAddress((void**)&pfe,   g_fe);
    cudaGetSymbolAddress((void**)&pzbase,g_z);
    cudaGetSymbolAddress((void**)&pznb,  g_zn);
    cudaGetSymbolAddress((void**)&pout1, g_out1);
    cudaGetSymbolAddress((void**)&pwbuf, g_wbuf);
    cudaGetSymbolAddress((void**)&rp_nd, g_rp_nd);
    cudaGetSymbolAddress((void**)&ci_nd, g_ci_nd);
    cudaGetSymbolAddress((void**)&rp_fn, g_rp_fn);
    cudaGetSymbolAddress((void**)&ci_fn, g_ci_fn);
    cudaGetSymbolAddress((void**)&rp_lg, g_rp_lg);
    cudaGetSymbolAddress((void**)&ci_lg, g_ci_lg);
    cudaGetSymbolAddress((void**)&pcnt,  g_cnt);
    cudaGetSymbolAddress((void**)&pcur,  g_cur);
    cudaGetSymbolAddress((void**)&pbs,   g_bs);

    n.wbuf = pwbuf;
    n.pout1 = pout1;
    float* px[2]  = {px0,  px0  + (size_t)NNODE * H};
    float* plg[2] = {plg0, plg0 + (size_t)NEDGE * H};
    float* ze[4], * zn[4];
    for (int i = 0; i < 4; i++) {
        ze[i] = pzbase + (size_t)i * NEDGE * H;
        zn[i] = pznb + (size_t)i * NNODE * H;
    }

    const int* src_g = eig;  const int* dst_g = eig + NEDGE;
    const int* src_l = eil;  const int* dst_l = eil + NLG;

    // --- lg CSR build FIRST (so ncu -s 5 lands on the hot segsum path) ---
    cudaMemsetAsync(pcnt, 0, NEDGE * sizeof(int), 0);
    hist_kernel<<<(NLG + 255) / 256, 256>>>(dst_l, pcnt, NLG);
    exclusive_scan(pcnt, rp_lg, pbs, NEDGE);
    cudaMemcpyAsync(pcur, rp_lg, NEDGE * sizeof(int), cudaMemcpyDeviceToDevice, 0);
    fill_kernel<<<(NLG + 255) / 256, 256>>>(dst_l, src_l, pcur, ci_lg, NLG);

    // --- layer-0 edge-core khops (hop1 straight from rel table) ---
    segsum_rel_kernel<<<(NEDGE + 7) / 8, 256>>>(rel, feat, rp_lg, ci_lg, ze[0], NEDGE);
    segsum_kernel<<<(NEDGE + 7) / 8, 256>>>(ze[0], rp_lg, ci_lg, ze[1], NEDGE);
    segsum_kernel<<<(NEDGE + 7) / 8, 256>>>(ze[1], rp_lg, ci_lg, ze[2], NEDGE);
    segsum_kernel<<<(NEDGE + 7) / 8, 256>>>(ze[2], rp_lg, ci_lg, ze[3], NEDGE);

    // --- pack weights (tf32 round + fragment permutation) ---
    pack256_kernel<<<(4 * 16384 + 255) / 256, 256>>>(w_self, pwbuf + OFF_WSELF, 4);
    pack256_kernel<<<(16 * 16384 + 255) / 256, 256>>>(w_khop, pwbuf + OFF_WKHOP, 16);
    pack256_kernel<<<(4 * 16384 + 255) / 256, 256>>>(w_fuse, pwbuf + OFF_WFUSE, 4);
    packff1_kernel<<<(4 * 65536 + 255) / 256, 256>>>(w_ff1, pwbuf + OFF_WFF1, 4);
    packff2_kernel<<<(4 * 65536 + 255) / 256, 256>>>(w_ff2, pwbuf + OFF_WFF2, 4);

    // --- init states ---
    cvt_kernel<<<(NNODE * H / 4 + 255) / 256, 256>>>(x_in, px[0], NNODE * H / 4);
    embed_kernel<<<NEDGE * 64 / 256, 256>>>(rel, feat, plg[0]);

    // --- node + fused-node CSR builds ---
    cudaMemsetAsync(pcnt, 0, NNODE * sizeof(int), 0);
    hist_kernel<<<(NEDGE + 255) / 256, 256>>>(dst_g, pcnt, NEDGE);
    exclusive_scan(pcnt, rp_nd, pbs, NNODE);
    cudaMemcpyAsync(pcur, rp_nd, NNODE * sizeof(int), cudaMemcpyDeviceToDevice, 0);
    fill_kernel<<<(NEDGE + 255) / 256, 256>>>(dst_g, src_g, pcur, ci_nd, NEDGE);

    cudaMemsetAsync(pcnt, 0, NNODE * sizeof(int), 0);
    hist_kernel<<<(NEDGE + 255) / 256, 256>>>(src_g, pcnt, NEDGE);
    hist_kernel<<<(NEDGE + 255) / 256, 256>>>(dst_g, pcnt, NEDGE);
    exclusive_scan(pcnt, rp_fn, pbs, NNODE);
    cudaMemcpyAsync(pcur, rp_fn, NNODE * sizeof(int), cudaMemcpyDeviceToDevice, 0);
    fill_kernel<<<(NEDGE + 255) / 256, 256>>>(src_g, nullptr, pcur, ci_fn, NEDGE);
    fill_kernel<<<(NEDGE + 255) / 256, 256>>>(dst_g, nullptr, pcur, ci_fn, NEDGE);

    // --- layers ---
    for (int l = 0; l < 2; l++) {
        float* xcur  = px[l & 1];
        float* lgcur = plg[l & 1];
        int last = (l == 1);
        float* xout  = last ? (float*)d_out : px[(l + 1) & 1];
        float* lgout = last ? (float*)d_out + (size_t)NNODE * H : plg[(l + 1) & 1];

        // fused features
        segsum_kernel<<<(NNODE + 7) / 8, 256>>>(lgcur, rp_fn, ci_fn, pfn, NNODE);
        gather2_kernel<<<NEDGE * 64 / 256, 256>>>(xcur, src_g, dst_g, pfe, NEDGE);

        // node-core khops
        {
            const float* prev = xcur;
            for (int i = 0; i < 4; i++) {
                segsum_kernel<<<(NNODE + 7) / 8, 256>>>(prev, rp_nd, ci_nd, zn[i], NNODE);
                prev = zn[i];
            }
        }
        run_core(n, l, 0, NNODE, zn, xcur, pfn, xout, !last);

        // edge-core khops (layer 0 already computed up front)
        if (l == 1) {
            const float* prev = lgcur;
            for (int i = 0; i < 4; i++) {
                segsum_kernel<<<(NEDGE + 7) / 8, 256>>>(prev, rp_lg, ci_lg, ze[i], NEDGE);
                prev = ze[i];
            }
        }
        run_core(n, l, 1, NEDGE, ze, lgcur, pfe, lgout, !last);
    }
    (void)in_sizes; (void)n_in; (void)out_size;
}

// round 7
// speedup vs baseline: 1.1887x; 1.0557x over previous
#include <cuda_runtime.h>
#include <cstdint>
#include <math.h>

#define H       256
#define FH      1024
#define NNODE   20000
#define NEDGE   160000
#define NLG     640000

// ---------------- scratch (static device memory; no allocations) ----------------
__device__ float g_x[2][(size_t)NNODE * H];
__device__ float g_lg[2][(size_t)NEDGE * H];
__device__ float g_fn[(size_t)NNODE * H];
__device__ float g_fe[(size_t)NEDGE * H];
__device__ float g_z[4][(size_t)NEDGE * H];    // edge-core khop scratch
__device__ float g_zn[4][(size_t)NNODE * H];   // node-core khop scratch
__device__ float g_out1[(size_t)NEDGE * H];    // edge-core out1
__device__ float g_out1n[(size_t)NNODE * H];   // node-core out1 (stream overlap)

// packed (tf32-rounded, fragment-order) weights
#define OFF_WSELF 0
#define OFF_WKHOP (OFF_WSELF + 4 * H * H)
#define OFF_WFUSE (OFF_WKHOP + 16 * H * H)
#define OFF_WFF1  (OFF_WFUSE + 4 * H * H)
#define OFF_WFF2  (OFF_WFF1 + 4 * H * FH)
#define WBUF_TOT  (OFF_WFF2 + 4 * FH * H)
__device__ float g_wbuf[WBUF_TOT];

// CSR structures
__device__ int g_rp_nd[NNODE + 1];
__device__ int g_ci_nd[NEDGE];
__device__ int g_rp_fn[NNODE + 1];
__device__ int g_ci_fn[2 * NEDGE];
__device__ int g_rp_lg[NEDGE + 1];
__device__ int g_ci_lg[NLG];
__device__ int g_cnt[NEDGE];
__device__ int g_cur[NEDGE];
__device__ int g_bs[1024];

__device__ __forceinline__ float gelu_exact(float v) {
    return 0.5f * v * (1.0f + erff(v * 0.70710678118654752f));
}

__device__ __forceinline__ float f2tf32f(float f) {
    uint32_t r;
    asm("cvt.rna.tf32.f32 %0, %1;" : "=r"(r) : "f"(f));
    return __uint_as_float(r);
}

__device__ __forceinline__ void mma_tf32(float* c, const uint32_t* a, const uint32_t* b) {
    asm volatile(
        "mma.sync.aligned.m16n8k8.row.col.f32.tf32.tf32.f32 "
        "{%0,%1,%2,%3}, {%4,%5,%6,%7}, {%8,%9}, {%0,%1,%2,%3};"
        : "+f"(c[0]), "+f"(c[1]), "+f"(c[2]), "+f"(c[3])
        : "r"(a[0]), "r"(a[1]), "r"(a[2]), "r"(a[3]), "r"(b[0]), "r"(b[1]));
}

// ---------------- CSR build kernels ----------------

__global__ void hist_kernel(const int* __restrict__ key, int* cnt, int n) {
    int i = blockIdx.x * 256 + threadIdx.x;
    if (i < n) atomicAdd(&cnt[__ldg(key + i)], 1);
}

__global__ void scan1_kernel(const int* __restrict__ in, int* __restrict__ out,
                             int* __restrict__ bsums, int n) {
    __shared__ int sh[1024];
    int i = blockIdx.x * 1024 + threadIdx.x;
    int v = (i < n) ? in[i] : 0;
    sh[threadIdx.x] = v;
    __syncthreads();
#pragma unroll
    for (int o = 1; o < 1024; o <<= 1) {
        int t = (threadIdx.x >= o) ? sh[threadIdx.x - o] : 0;
        __syncthreads();
        sh[threadIdx.x] += t;
        __syncthreads();
    }
    if (i < n) out[i] = sh[threadIdx.x] - v;     // exclusive
    if (threadIdx.x == 1023) bsums[blockIdx.x] = sh[1023];
}

__global__ void scan2_kernel(int* bsums, int nb) {
    __shared__ int sh[1024];
    int v = (threadIdx.x < nb) ? bsums[threadIdx.x] : 0;
    sh[threadIdx.x] = v;
    __syncthreads();
#pragma unroll
    for (int o = 1; o < 1024; o <<= 1) {
        int t = (threadIdx.x >= o) ? sh[threadIdx.x - o] : 0;
        __syncthreads();
        sh[threadIdx.x] += t;
        __syncthreads();
    }
    if (threadIdx.x < nb) bsums[threadIdx.x] = sh[threadIdx.x] - v;  // exclusive
}

__global__ void scan3_kernel(int* __restrict__ out, const int* __restrict__ bsums,
                             const int* __restrict__ cnt, int n) {
    int i = blockIdx.x * 1024 + threadIdx.x;
    if (i < n) {
        int v = out[i] + bsums[i >> 10];
        out[i] = v;
        if (i == n - 1) out[n] = v + cnt[i];
    }
}

__global__ void fill_kernel(const int* __restrict__ key, const int* __restrict__ val,
                            int* cursor, int* __restrict__ ci, int n) {
    int i = blockIdx.x * 256 + threadIdx.x;
    if (i >= n) return;
    int pos = atomicAdd(&cursor[__ldg(key + i)], 1);
    ci[pos] = val ? __ldg(val + i) : i;
}

// ---------------- weight pack kernels (tf32 round + fragment permutation) ----------------
// float4 = { W[k][n], W[k+4][n], W[k][n+8], W[k+4][n+8] }, k = kt*32+ks*8+t

// H x H (gemm1 weights), m32n64 warp tile: [kt(8)][ks(4)][wN(4)][nf2(4)][lane(32)]
__global__ void pack256_kernel(const float* __restrict__ W, float* __restrict__ out, int nmat) {
    int gid = blockIdx.x * 256 + threadIdx.x;
    if (gid >= nmat * 16384) return;
    int m = gid >> 14, o = gid & 16383;
    int kt = o >> 11, i4 = o & 2047;
    int ks = i4 >> 9, r = i4 & 511;
    int wN = r >> 7, r2 = r & 127;
    int nf2 = r2 >> 5, lane = r2 & 31;
    int t = lane & 3, g = lane >> 2;
    int k = kt * 32 + ks * 8 + t;
    int n = wN * 64 + nf2 * 16 + g;
    const float* Wm = W + (size_t)m * 65536;
    float4 v;
    v.x = f2tf32f(Wm[k * 256 + n]);
    v.y = f2tf32f(Wm[(k + 4) * 256 + n]);
    v.z = f2tf32f(Wm[k * 256 + n + 8]);
    v.w = f2tf32f(Wm[(k + 4) * 256 + n + 8]);
    ((float4*)out)[gid] = v;
}

// w_ff1 [256, 1024]: [c(8)][kt(8)][ks(4)][wN(4)][nf2(2)][lane] float4
__global__ void packff1_kernel(const float* __restrict__ W, float* __restrict__ out, int nmat) {
    int gid = blockIdx.x * 256 + threadIdx.x;
    if (gid >= nmat * 65536) return;
    int m = gid >> 16, o = gid & 65535;
    int c = o >> 13, r = o & 8191;
    int kt = r >> 10, i4 = r & 1023;
    int ks = i4 >> 8, r2 = i4 & 255;
    int wN = r2 >> 6, r3 = r2 & 63;
    int nf2 = r3 >> 5, lane = r3 & 31;
    int t = lane & 3, g = lane >> 2;
    int k = kt * 32 + ks * 8 + t;
    int n = c * 128 + wN * 32 + nf2 * 16 + g;
    const float* Wm = W + (size_t)m * 262144;
    float4 v;
    v.x = f2tf32f(Wm[k * 1024 + n]);
    v.y = f2tf32f(Wm[(k + 4) * 1024 + n]);
    v.z = f2tf32f(Wm[k * 1024 + n + 8]);
    v.w = f2tf32f(Wm[(k + 4) * 1024 + n + 8]);
    ((float4*)out)[gid] = v;
}

// w_ff2 [1024, 256]: [c(8)][kt(4)][ks(4)][wN(4)][nf2(4)][lane] float4
__global__ void packff2_kernel(const float* __restrict__ W, float* __restrict__ out, int nmat) {
    int gid = blockIdx.x * 256 + threadIdx.x;
    if (gid >= nmat * 65536) return;
    int m = gid >> 16, o = gid & 65535;
    int c = o >> 13, r = o & 8191;
    int kt = r >> 11, i4 = r & 2047;
    int ks = i4 >> 9, r2 = i4 & 511;
    int wN = r2 >> 7, r3 = r2 & 127;
    int nf2 = r3 >> 5, lane = r3 & 31;
    int t = lane & 3, g = lane >> 2;
    int k = c * 128 + kt * 32 + ks * 8 + t;
    int n = wN * 64 + nf2 * 16 + g;
    const float* Wm = W + (size_t)m * 262144;
    float4 v;
    v.x = f2tf32f(Wm[k * 256 + n]);
    v.y = f2tf32f(Wm[(k + 4) * 256 + n]);
    v.z = f2tf32f(Wm[k * 256 + n + 8]);
    v.w = f2tf32f(Wm[(k + 4) * 256 + n + 8]);
    ((float4*)out)[gid] = v;
}

// ---------------- small kernels ----------------

__global__ void cvt_kernel(const float* __restrict__ in, float* __restrict__ out, int n4) {
    int i = blockIdx.x * 256 + threadIdx.x;
    if (i >= n4) return;
    float4 v = ((const float4*)in)[i];
    v.x = f2tf32f(v.x); v.y = f2tf32f(v.y); v.z = f2tf32f(v.z); v.w = f2tf32f(v.w);
    ((float4*)out)[i] = v;
}

__global__ void embed_kernel(const float* __restrict__ rel, const int* __restrict__ feat,
                             float* __restrict__ out) {
    int gid = blockIdx.x * blockDim.x + threadIdx.x;
    int e = gid >> 6;
    if (e >= NEDGE) return;
    int c = (gid & 63) << 2;
    int r = __ldg(feat + e);
    float4 v = *(const float4*)(rel + (size_t)r * H + c);
    v.x = f2tf32f(v.x); v.y = f2tf32f(v.y); v.z = f2tf32f(v.z); v.w = f2tf32f(v.w);
    *(float4*)(out + (size_t)e * H + c) = v;
}

__global__ void gather2_kernel(const float* __restrict__ x, const int* __restrict__ s,
                               const int* __restrict__ d, float* __restrict__ out, int n) {
    int gid = blockIdx.x * blockDim.x + threadIdx.x;
    int e = gid >> 6;
    if (e >= n) return;
    int c = (gid & 63) << 2;
    int si = __ldg(s + e), di = __ldg(d + e);
    float4 a = *(const float4*)(x + (size_t)si * H + c);
    float4 b = *(const float4*)(x + (size_t)di * H + c);
    a.x = f2tf32f(a.x + b.x); a.y = f2tf32f(a.y + b.y);
    a.z = f2tf32f(a.z + b.z); a.w = f2tf32f(a.w + b.w);
    *(float4*)(out + (size_t)e * H + c) = a;
}

// CSR gather segment-sum (2-way unrolled)
__global__ void segsum_kernel(const float* __restrict__ rows, const int* __restrict__ rp,
                              const int* __restrict__ ci, float* __restrict__ out, int nseg) {
    int row = blockIdx.x * 8 + (threadIdx.x >> 5);
    if (row >= nseg) return;
    int lane = threadIdx.x & 31;
    int beg = __ldg(rp + row), end = __ldg(rp + row + 1);
    float a[8] = {0.f, 0.f, 0.f, 0.f, 0.f, 0.f, 0.f, 0.f};
    float b[8] = {0.f, 0.f, 0.f, 0.f, 0.f, 0.f, 0.f, 0.f};
    int j = beg;
    for (; j + 1 < end; j += 2) {
        const float* p0 = rows + (size_t)__ldg(ci + j) * H + lane * 8;
        const float* p1 = rows + (size_t)__ldg(ci + j + 1) * H + lane * 8;
        float4 u0 = ((const float4*)p0)[0], u1 = ((const float4*)p0)[1];
        float4 w0 = ((const float4*)p1)[0], w1 = ((const float4*)p1)[1];
        a[0] += u0.x; a[1] += u0.y; a[2] += u0.z; a[3] += u0.w;
        a[4] += u1.x; a[5] += u1.y; a[6] += u1.z; a[7] += u1.w;
        b[0] += w0.x; b[1] += w0.y; b[2] += w0.z; b[3] += w0.w;
        b[4] += w1.x; b[5] += w1.y; b[6] += w1.z; b[7] += w1.w;
    }
    if (j < end) {
        const float* p0 = rows + (size_t)__ldg(ci + j) * H + lane * 8;
        float4 u0 = ((const float4*)p0)[0], u1 = ((const float4*)p0)[1];
        a[0] += u0.x; a[1] += u0.y; a[2] += u0.z; a[3] += u0.w;
        a[4] += u1.x; a[5] += u1.y; a[6] += u1.z; a[7] += u1.w;
    }
#pragma unroll
    for (int i = 0; i < 8; i++) a[i] = f2tf32f(a[i] + b[i]);
    float* po = out + (size_t)row * H + lane * 8;
    ((float4*)po)[0] = make_float4(a[0], a[1], a[2], a[3]);
    ((float4*)po)[1] = make_float4(a[4], a[5], a[6], a[7]);
}

// hop1 of layer-0 edge core: gather rel[feat[ci[j]]]
__global__ void segsum_rel_kernel(const float* __restrict__ rel, const int* __restrict__ feat,
                                  const int* __restrict__ rp, const int* __restrict__ ci,
                                  float* __restrict__ out, int nseg) {
    int row = blockIdx.x * 8 + (threadIdx.x >> 5);
    if (row >= nseg) return;
    int lane = threadIdx.x & 31;
    int beg = __ldg(rp + row), end = __ldg(rp + row + 1);
    float a[8] = {0.f, 0.f, 0.f, 0.f, 0.f, 0.f, 0.f, 0.f};
    for (int j = beg; j < end; j++) {
        int r = __ldg(feat + __ldg(ci + j));
        const float* p = rel + (size_t)r * H + lane * 8;
        float4 u0 = ((const float4*)p)[0], u1 = ((const float4*)p)[1];
        a[0] += f2tf32f(u0.x); a[1] += f2tf32f(u0.y);
        a[2] += f2tf32f(u0.z); a[3] += f2tf32f(u0.w);
        a[4] += f2tf32f(u1.x); a[5] += f2tf32f(u1.y);
        a[6] += f2tf32f(u1.z); a[7] += f2tf32f(u1.w);
    }
#pragma unroll
    for (int i = 0; i < 8; i++) a[i] = f2tf32f(a[i]);
    float* po = out + (size_t)row * H + lane * 8;
    ((float4*)po)[0] = make_float4(a[0], a[1], a[2], a[3]);
    ((float4*)po)[1] = make_float4(a[4], a[5], a[6], a[7]);
}

// ================= GEMM1 + LN1 fused, m32n64 warp tile =================
// out1 = tf32( LN( xres + gelu( sum_j A_j @ W_j + sum_j bias_j ) ) )
// BM=64, BN=256, 256 threads, warps: 2 along M (m32) x 4 along N (n64).

#define G_ASTR 36
#define G_AST (64 * G_ASTR)       // 2304
#define G_BST 8192
#define G1_SMEM_FLOATS (2 * G_AST + 2 * G_BST + 3 * 256 + 2 * 256)
#define G1_SMEM_BYTES (G1_SMEM_FLOATS * 4)

struct G1Args {
    const float* A[6];
    const float* W[6];       // packed
    const float* Bias[6];
    const float* xres;
    const float* gamma;
    const float* beta;
};

__global__ void __launch_bounds__(256, 2)
gemm1_ln_kernel(G1Args args, int M, float* __restrict__ out) {
    extern __shared__ float sm[];
    float* As = sm;
    float* Bs = sm + 2 * G_AST;
    float* bias_s = Bs + 2 * G_BST;
    float* gs = bias_s + 256;
    float* bt = gs + 256;
    float* lnS = bt + 256;
    float* lnQ = lnS + 256;
    float* xs = sm;                 // alias; reused after mainloop, stride 264

    int tid = threadIdx.x;
    int bm = blockIdx.x * 64;

    {
        float b = 0.f;
#pragma unroll
        for (int j = 0; j < 6; j++) b += __ldg(args.Bias[j] + tid);
        bias_s[tid] = b;
        gs[tid] = __ldg(args.gamma + tid);
        bt[tid] = __ldg(args.beta + tid);
    }

    uint32_t a_base = (uint32_t)__cvta_generic_to_shared(As);
    uint32_t b_base = (uint32_t)__cvta_generic_to_shared(Bs);

    int warp = tid >> 5, lane = tid & 31, g = lane >> 2, t = lane & 3;
    int wm = (warp >> 2) * 32;    // 2 warps along M, 32 rows each
    int wN = warp & 3;            // 4 warps along N, 64 cols each
    int wn = wN * 64;

    float acc[2][8][4];
#pragma unroll
    for (int mt = 0; mt < 2; mt++)
#pragma unroll
        for (int nf = 0; nf < 8; nf++)
#pragma unroll
            for (int i = 0; i < 4; i++) acc[mt][nf][i] = 0.f;

    auto issue = [&](int tt, int buf) {
        int j = tt >> 3;
        int kk = (tt & 7) * 32;
        const float* A = args.A[j];
        const float4* Wp = (const float4*)args.W[j] + (size_t)(tt & 7) * 2048;
#pragma unroll
        for (int i = 0; i < 2; i++) {
            int idx = tid + i * 256;
            int r = idx >> 3, kv = (idx & 7) << 2;
            int row = bm + r;
            uint32_t dst = a_base + (uint32_t)((buf * G_AST + r * G_ASTR + kv) * 4);
            const float* src = A + (size_t)row * H + kk + kv;
            int sz = (row < M) ? 16 : 0;
            asm volatile("cp.async.cg.shared.global [%0], [%1], 16, %2;\n"
                         :: "r"(dst), "l"(src), "r"(sz));
        }
#pragma unroll
        for (int i = 0; i < 8; i++) {
            int idx = tid + i * 256;
            uint32_t dst = b_base + (uint32_t)((buf * G_BST + idx * 4) * 4);
            asm volatile("cp.async.cg.shared.global [%0], [%1], 16;\n"
                         :: "r"(dst), "l"(Wp + idx));
        }
        asm volatile("cp.async.commit_group;\n");
    };

    issue(0, 0);
    for (int tt = 0; tt < 48; tt++) {
        if (tt + 1 < 48) {
            issue(tt + 1, (tt + 1) & 1);
            asm volatile("cp.async.wait_group 1;\n");
        } else {
            asm volatile("cp.async.wait_group 0;\n");
        }
        __syncthreads();
        const float* Ab = As + (tt & 1) * G_AST;
        const float4* Bb4 = (const float4*)(Bs + (tt & 1) * G_BST) + wN * 128 + lane;
#pragma unroll
        for (int ks = 0; ks < 4; ks++) {
            int k0 = ks * 8;
            uint32_t a0[4], a1[4];
            a0[0] = __float_as_uint(Ab[(wm + g) * G_ASTR + k0 + t]);
            a0[1] = __float_as_uint(Ab[(wm + 8 + g) * G_ASTR + k0 + t]);
            a0[2] = __float_as_uint(Ab[(wm + g) * G_ASTR + k0 + t + 4]);
            a0[3] = __float_as_uint(Ab[(wm + 8 + g) * G_ASTR + k0 + t + 4]);
            a1[0] = __float_as_uint(Ab[(wm + 16 + g) * G_ASTR + k0 + t]);
            a1[1] = __float_as_uint(Ab[(wm + 24 + g) * G_ASTR + k0 + t]);
            a1[2] = __float_as_uint(Ab[(wm + 16 + g) * G_ASTR + k0 + t + 4]);
            a1[3] = __float_as_uint(Ab[(wm + 24 + g) * G_ASTR + k0 + t + 4]);
#pragma unroll
            for (int nf2 = 0; nf2 < 4; nf2++) {
                float4 bv = Bb4[ks * 512 + nf2 * 32];
                uint32_t b0[2] = {__float_as_uint(bv.x), __float_as_uint(bv.y)};
                mma_tf32(acc[0][2 * nf2], a0, b0);
                mma_tf32(acc[1][2 * nf2], a1, b0);
                uint32_t b1[2] = {__float_as_uint(bv.z), __float_as_uint(bv.w)};
                mma_tf32(acc[0][2 * nf2 + 1], a0, b1);
                mma_tf32(acc[1][2 * nf2 + 1], a1, b1);
            }
        }
        __syncthreads();
    }

    // cooperative residual tile load into xs (stride 264)
#pragma unroll
    for (int i = 0; i < 16; i++) {
        int idx = tid + i * 256;
        int r = idx >> 6, cv = (idx & 63) << 2;
        int row = bm + r;
        float4 v = make_float4(0.f, 0.f, 0.f, 0.f);
        if (row < M) v = *(const float4*)(args.xres + (size_t)row * H + cv);
        *(float4*)(xs + r * 264 + cv) = v;
    }
    __syncthreads();

    // bias+gelu+residual, per-row partial sums
#pragma unroll
    for (int mt = 0; mt < 2; mt++) {
#pragma unroll
        for (int h = 0; h < 2; h++) {
            int row = wm + mt * 16 + h * 8 + g;
            float s = 0.f, q = 0.f;
#pragma unroll
            for (int nf = 0; nf < 8; nf++) {
                int col = wn + nf * 8 + 2 * t;
                float v0 = xs[row * 264 + col]     + gelu_exact(acc[mt][nf][2 * h]     + bias_s[col]);
                float v1 = xs[row * 264 + col + 1] + gelu_exact(acc[mt][nf][2 * h + 1] + bias_s[col + 1]);
                acc[mt][nf][2 * h] = v0; acc[mt][nf][2 * h + 1] = v1;
                s += v0 + v1; q += v0 * v0 + v1 * v1;
            }
#pragma unroll
            for (int o = 1; o <= 2; o <<= 1) {
                s += __shfl_xor_sync(0xffffffffu, s, o);
                q += __shfl_xor_sync(0xffffffffu, q, o);
            }
            if (t == 0) { lnS[row * 4 + wN] = s; lnQ[row * 4 + wN] = q; }
        }
    }
    __syncthreads();
#pragma unroll
    for (int mt = 0; mt < 2; mt++) {
#pragma unroll
        for (int h = 0; h < 2; h++) {
            int row = wm + mt * 16 + h * 8 + g;
            float S = lnS[row * 4] + lnS[row * 4 + 1] + lnS[row * 4 + 2] + lnS[row * 4 + 3];
            float Q = lnQ[row * 4] + lnQ[row * 4 + 1] + lnQ[row * 4 + 2] + lnQ[row * 4 + 3];
            float m = S * (1.f / H), v = Q * (1.f / H) - m * m, rs = rsqrtf(v + 1e-5f);
            if (bm + row < M) {
#pragma unroll
                for (int nf = 0; nf < 8; nf++) {
                    int col = wn + nf * 8 + 2 * t;
                    float o0 = f2tf32f((acc[mt][nf][2 * h]     - m) * rs * gs[col]     + bt[col]);
                    float o1 = f2tf32f((acc[mt][nf][2 * h + 1] - m) * rs * gs[col + 1] + bt[col + 1]);
                    *(float2*)(out + (size_t)(bm + row) * H + col) = make_float2(o0, o1);
                }
            }
        }
    }
}

// ================= fused FFN + LN2 =================
#define F_XSTR 260
#define F_HSTR 132
#define F_B1ST 4096
#define F_B2ST 8192
#define F_SMEM_FLOATS (64 * F_XSTR + 64 * F_HSTR + 2 * F_B2ST + 3 * 256 + 128 + 2 * 256)
#define F_SMEM_BYTES (F_SMEM_FLOATS * 4)

struct FArgs {
    const float* w1;    // packed
    const float* b1;
    const float* w2;    // packed
    const float* b2;
    const float* gamma;
    const float* beta;
};

__global__ void __launch_bounds__(512, 1)
ffn_kernel(FArgs args, int M, const float* __restrict__ in1,
           float* __restrict__ out, int out_cvt) {
    extern __shared__ float sm[];
    float* xs  = sm;
    float* hb  = xs + 64 * F_XSTR;
    float* Bst = hb + 64 * F_HSTR;
    float* b2s = Bst + 2 * F_B2ST;
    float* gs  = b2s + 256;
    float* bt  = gs + 256;
    float* b1c = bt + 256;
    float* lnS = b1c + 128;
    float* lnQ = lnS + 256;

    int tid = threadIdx.x;
    int bm = blockIdx.x * 64;

    if (tid < 256) {
        b2s[tid] = __ldg(args.b2 + tid);
        gs[tid]  = __ldg(args.gamma + tid);
        bt[tid]  = __ldg(args.beta + tid);
    }
#pragma unroll
    for (int i = 0; i < 8; i++) {
        int idx = tid + i * 512;
        int r = idx >> 6, cv = (idx & 63) << 2;
        int row = bm + r;
        float4 v = make_float4(0.f, 0.f, 0.f, 0.f);
        if (row < M) v = *(const float4*)(in1 + (size_t)row * H + cv);
        *(float4*)(xs + r * F_XSTR + cv) = v;
    }

    uint32_t bst_base = (uint32_t)__cvta_generic_to_shared(Bst);
    int warp = tid >> 5, lane = tid & 31, g = lane >> 2, t = lane & 3;
    int wm = (warp >> 2) * 16;
    int wN = warp & 3;
    int wn1 = wN * 32;
    int wn2 = wN * 64;

    float acc2[8][4];
#pragma unroll
    for (int nf = 0; nf < 8; nf++)
#pragma unroll
        for (int i = 0; i < 4; i++) acc2[nf][i] = 0.f;

    __syncthreads();

    for (int c = 0; c < 8; c++) {
        if (tid < 128) b1c[tid] = __ldg(args.b1 + c * 128 + tid);

        float acc1[4][4];
#pragma unroll
        for (int nf = 0; nf < 4; nf++)
#pragma unroll
            for (int i = 0; i < 4; i++) acc1[nf][i] = 0.f;

        const float4* W1p = (const float4*)args.w1 + (size_t)c * 8192;
        auto issue1 = [&](int kt, int buf) {
#pragma unroll
            for (int i = 0; i < 2; i++) {
                int idx = tid + i * 512;
                uint32_t dst = bst_base + (uint32_t)((buf * F_B1ST + idx * 4) * 4);
                asm volatile("cp.async.cg.shared.global [%0], [%1], 16;\n"
                             :: "r"(dst), "l"(W1p + kt * 1024 + idx));
            }
            asm volatile("cp.async.commit_group;\n");
        };

        issue1(0, 0);
        for (int kt = 0; kt < 8; kt++) {
            if (kt + 1 < 8) {
                issue1(kt + 1, (kt + 1) & 1);
                asm volatile("cp.async.wait_group 1;\n");
            } else {
                asm volatile("cp.async.wait_group 0;\n");
            }
            __syncthreads();
            const float4* Bb4 = (const float4*)(Bst + (kt & 1) * F_B1ST) + wN * 64 + lane;
            int kk = kt * 32;
#pragma unroll
            for (int ks = 0; ks < 4; ks++) {
                int kg = kk + ks * 8;
                uint32_t a[4];
                a[0] = __float_as_uint(xs[(wm + g) * F_XSTR + kg + t]);
                a[1] = __float_as_uint(xs[(wm + 8 + g) * F_XSTR + kg + t]);
                a[2] = __float_as_uint(xs[(wm + g) * F_XSTR + kg + t + 4]);
                a[3] = __float_as_uint(xs[(wm + 8 + g) * F_XSTR + kg + t + 4]);
#pragma unroll
                for (int nf2 = 0; nf2 < 2; nf2++) {
                    float4 bv = Bb4[ks * 256 + nf2 * 32];
                    uint32_t b0[2] = {__float_as_uint(bv.x), __float_as_uint(bv.y)};
                    mma_tf32(acc1[2 * nf2], a, b0);
                    uint32_t b1[2] = {__float_as_uint(bv.z), __float_as_uint(bv.w)};
                    mma_tf32(acc1[2 * nf2 + 1], a, b1);
                }
            }
            __syncthreads();
        }

#pragma unroll
        for (int nf = 0; nf < 4; nf++) {
            int col = wn1 + nf * 8 + 2 * t;
            float h0 = f2tf32f(gelu_exact(acc1[nf][0] + b1c[col]));
            float h1 = f2tf32f(gelu_exact(acc1[nf][1] + b1c[col + 1]));
            float h2 = f2tf32f(gelu_exact(acc1[nf][2] + b1c[col]));
            float h3 = f2tf32f(gelu_exact(acc1[nf][3] + b1c[col + 1]));
            *(float2*)(hb + (wm + g) * F_HSTR + col)     = make_float2(h0, h1);
            *(float2*)(hb + (wm + 8 + g) * F_HSTR + col) = make_float2(h2, h3);
        }
        __syncthreads();

        const float4* W2p = (const float4*)args.w2 + (size_t)c * 8192;
        auto issue2 = [&](int kt, int buf) {
#pragma unroll
            for (int i = 0; i < 4; i++) {
                int idx = tid + i * 512;
                uint32_t dst = bst_base + (uint32_t)((buf * F_B2ST + idx * 4) * 4);
                asm volatile("cp.async.cg.shared.global [%0], [%1], 16;\n"
                             :: "r"(dst), "l"(W2p + kt * 2048 + idx));
            }
            asm volatile("cp.async.commit_group;\n");
        };

        issue2(0, 0);
        for (int kt = 0; kt < 4; kt++) {
            if (kt + 1 < 4) {
                issue2(kt + 1, (kt + 1) & 1);
                asm volatile("cp.async.wait_group 1;\n");
            } else {
                asm volatile("cp.async.wait_group 0;\n");
            }
            __syncthreads();
            const float4* Bb4 = (const float4*)(Bst + (kt & 1) * F_B2ST) + wN * 128 + lane;
            int kk = kt * 32;
#pragma unroll
            for (int ks = 0; ks < 4; ks++) {
                int kg = kk + ks * 8;
                uint32_t a[4];
                a[0] = __float_as_uint(hb[(wm + g) * F_HSTR + kg + t]);
                a[1] = __float_as_uint(hb[(wm + 8 + g) * F_HSTR + kg + t]);
                a[2] = __float_as_uint(hb[(wm + g) * F_HSTR + kg + t + 4]);
                a[3] = __float_as_uint(hb[(wm + 8 + g) * F_HSTR + kg + t + 4]);
#pragma unroll
                for (int nf2 = 0; nf2 < 4; nf2++) {
                    float4 bv = Bb4[ks * 512 + nf2 * 32];
                    uint32_t b0[2] = {__float_as_uint(bv.x), __float_as_uint(bv.y)};
                    mma_tf32(acc2[2 * nf2], a, b0);
                    uint32_t b1[2] = {__float_as_uint(bv.z), __float_as_uint(bv.w)};
                    mma_tf32(acc2[2 * nf2 + 1], a, b1);
                }
            }
            __syncthreads();
        }
    }

    // LN2 epilogue
    int row0 = wm + g, row1 = wm + 8 + g;
    float s0 = 0.f, q0 = 0.f, s1 = 0.f, q1 = 0.f;
#pragma unroll
    for (int nf = 0; nf < 8; nf++) {
        int col = wn2 + nf * 8 + 2 * t;
        float t0 = xs[row0 * F_XSTR + col]     + acc2[nf][0] + b2s[col];
        float t1 = xs[row0 * F_XSTR + col + 1] + acc2[nf][1] + b2s[col + 1];
        float t2 = xs[row1 * F_XSTR + col]     + acc2[nf][2] + b2s[col];
        float t3 = xs[row1 * F_XSTR + col + 1] + acc2[nf][3] + b2s[col + 1];
        acc2[nf][0] = t0; acc2[nf][1] = t1; acc2[nf][2] = t2; acc2[nf][3] = t3;
        s0 += t0 + t1; q0 += t0 * t0 + t1 * t1;
        s1 += t2 + t3; q1 += t2 * t2 + t3 * t3;
    }
#pragma unroll
    for (int o = 1; o <= 2; o <<= 1) {
        s0 += __shfl_xor_sync(0xffffffffu, s0, o);
        q0 += __shfl_xor_sync(0xffffffffu, q0, o);
        s1 += __shfl_xor_sync(0xffffffffu, s1, o);
        q1 += __shfl_xor_sync(0xffffffffu, q1, o);
    }
    if (t == 0) {
        lnS[row0 * 4 + wN] = s0; lnQ[row0 * 4 + wN] = q0;
        lnS[row1 * 4 + wN] = s1; lnQ[row1 * 4 + wN] = q1;
    }
    __syncthreads();
    float S0 = lnS[row0 * 4] + lnS[row0 * 4 + 1] + lnS[row0 * 4 + 2] + lnS[row0 * 4 + 3];
    float Q0 = lnQ[row0 * 4] + lnQ[row0 * 4 + 1] + lnQ[row0 * 4 + 2] + lnQ[row0 * 4 + 3];
    float S1 = lnS[row1 * 4] + lnS[row1 * 4 + 1] + lnS[row1 * 4 + 2] + lnS[row1 * 4 + 3];
    float Q1 = lnQ[row1 * 4] + lnQ[row1 * 4 + 1] + lnQ[row1 * 4 + 2] + lnQ[row1 * 4 + 3];
    float m0 = S0 * (1.f / H), v0 = Q0 * (1.f / H) - m0 * m0, r0 = rsqrtf(v0 + 1e-5f);
    float m1 = S1 * (1.f / H), v1 = Q1 * (1.f / H) - m1 * m1, r1 = rsqrtf(v1 + 1e-5f);
    bool ok0 = (bm + row0) < M, ok1 = (bm + row1) < M;
#pragma unroll
    for (int nf = 0; nf < 8; nf++) {
        int col = wn2 + nf * 8 + 2 * t;
        float o0 = (acc2[nf][0] - m0) * r0 * gs[col]     + bt[col];
        float o1 = (acc2[nf][1] - m0) * r0 * gs[col + 1] + bt[col + 1];
        float o2 = (acc2[nf][2] - m1) * r1 * gs[col]     + bt[col];
        float o3 = (acc2[nf][3] - m1) * r1 * gs[col + 1] + bt[col + 1];
        if (out_cvt) {
            o0 = f2tf32f(o0); o1 = f2tf32f(o1);
            o2 = f2tf32f(o2); o3 = f2tf32f(o3);
        }
        if (ok0) *(float2*)(out + (size_t)(bm + row0) * H + col) = make_float2(o0, o1);
        if (ok1) *(float2*)(out + (size_t)(bm + row1) * H + col) = make_float2(o2, o3);
    }
}

// ---------------- host orchestration ----------------

struct Net {
    const float *b_self, *b_khop, *b_fuse, *b_ff1, *b_ff2;
    const float *ln1g, *ln1b, *ln2g, *ln2b;
    float* wbuf;
};

static void run_core(const Net& n, int l, int c, int M, float* const* z,
                     const float* xin, const float* fused, float* out1buf,
                     float* outp, int cvt_final, cudaStream_t st) {
    size_t lc = (size_t)(l * 2 + c);
    G1Args ga;
    ga.A[0] = xin;
    ga.W[0] = n.wbuf + OFF_WSELF + lc * H * H;
    ga.Bias[0] = n.b_self + lc * H;
    for (int i = 0; i < 4; i++) {
        ga.A[1 + i] = z[i];
        ga.W[1 + i] = n.wbuf + OFF_WKHOP + (lc * 4 + i) * (size_t)H * H;
        ga.Bias[1 + i] = n.b_khop + (lc * 4 + i) * (size_t)H;
    }
    ga.A[5] = fused;
    ga.W[5] = n.wbuf + OFF_WFUSE + lc * H * H;
    ga.Bias[5] = n.b_fuse + lc * H;
    ga.xres = xin;
    ga.gamma = n.ln1g + lc * H;
    ga.beta  = n.ln1b + lc * H;

    int grid = (M + 63) / 64;
    gemm1_ln_kernel<<<grid, 256, G1_SMEM_BYTES, st>>>(ga, M, out1buf);

    FArgs fa;
    fa.w1 = n.wbuf + OFF_WFF1 + lc * (size_t)H * FH;
    fa.b1 = n.b_ff1 + lc * FH;
    fa.w2 = n.wbuf + OFF_WFF2 + lc * (size_t)FH * H;
    fa.b2 = n.b_ff2 + lc * H;
    fa.gamma = n.ln2g + lc * H;
    fa.beta  = n.ln2b + lc * H;
    ffn_kernel<<<grid, 512, F_SMEM_BYTES, st>>>(fa, M, out1buf, outp, cvt_final);
}

static void exclusive_scan(int* cnt, int* rp, int* bsums, int n) {
    int nb = (n + 1023) / 1024;
    scan1_kernel<<<nb, 1024>>>(cnt, rp, bsums, n);
    scan2_kernel<<<1, 1024>>>(bsums, nb);
    scan3_kernel<<<nb, 1024>>>(rp, bsums, cnt, n);
}

extern "C" void kernel_launch(void* const* d_in, const int* in_sizes, int n_in,
                              void* d_out, int out_size) {
    const float* x_in = (const float*)d_in[0];
    const int* feat   = (const int*)d_in[1];
    const int* eig    = (const int*)d_in[2];
    const int* eil    = (const int*)d_in[3];
    const float* rel  = (const float*)d_in[4];

    const float* w_self = (const float*)d_in[5];
    const float* w_khop = (const float*)d_in[7];
    const float* w_fuse = (const float*)d_in[9];
    const float* w_ff1  = (const float*)d_in[11];
    const float* w_ff2  = (const float*)d_in[13];

    Net n;
    n.b_self = (const float*)d_in[6];
    n.b_khop = (const float*)d_in[8];
    n.b_fuse = (const float*)d_in[10];
    n.b_ff1  = (const float*)d_in[12];
    n.b_ff2  = (const float*)d_in[14];
    n.ln1g   = (const float*)d_in[15]; n.ln1b = (const float*)d_in[16];
    n.ln2g   = (const float*)d_in[17]; n.ln2b = (const float*)d_in[18];

    cudaFuncSetAttribute(gemm1_ln_kernel,
                         cudaFuncAttributeMaxDynamicSharedMemorySize, G1_SMEM_BYTES);
    cudaFuncSetAttribute(ffn_kernel,
                         cudaFuncAttributeMaxDynamicSharedMemorySize, F_SMEM_BYTES);

    // side stream + events (created once, outside capture on the first call)
    static cudaStream_t s2 = nullptr;
    static cudaEvent_t ev_init, ev_x0, ev_lg0, ev_fin;
    if (!s2) {
        cudaStreamCreateWithFlags(&s2, cudaStreamNonBlocking);
        cudaEventCreateWithFlags(&ev_init, cudaEventDisableTiming);
        cudaEventCreateWithFlags(&ev_x0,   cudaEventDisableTiming);
        cudaEventCreateWithFlags(&ev_lg0,  cudaEventDisableTiming);
        cudaEventCreateWithFlags(&ev_fin,  cudaEventDisableTiming);
    }

    float *px0, *plg0, *pfn, *pfe, *pzbase, *pznb, *pout1, *pout1n, *pwbuf;
    int *rp_nd, *ci_nd, *rp_fn, *ci_fn, *rp_lg, *ci_lg, *pcnt, *pcur, *pbs;
    cudaGetSymbolAddress((void**)&px0,   g_x);
    cudaGetSymbolAddress((void**)&plg0,  g_lg);
    cudaGetSymbolAddress((void**)&pfn,   g_fn);
    cudaGetSymbolAddress((void**)&pfe,   g_fe);
    cudaGetSymbolAddress((void**)&pzbase,g_z);
    cudaGetSymbolAddress((void**)&pznb,  g_zn);
    cudaGetSymbolAddress((void**)&pout1, g_out1);
    cudaGetSymbolAddress((void**)&pout1n,g_out1n);
    cudaGetSymbolAddress((void**)&pwbuf, g_wbuf);
    cudaGetSymbolAddress((void**)&rp_nd, g_rp_nd);
    cudaGetSymbolAddress((void**)&ci_nd, g_ci_nd);
    cudaGetSymbolAddress((void**)&rp_fn, g_rp_fn);
    cudaGetSymbolAddress((void**)&ci_fn, g_ci_fn);
    cudaGetSymbolAddress((void**)&rp_lg, g_rp_lg);
    cudaGetSymbolAddress((void**)&ci_lg, g_ci_lg);
    cudaGetSymbolAddress((void**)&pcnt,  g_cnt);
    cudaGetSymbolAddress((void**)&pcur,  g_cur);
    cudaGetSymbolAddress((void**)&pbs,   g_bs);

    n.wbuf = pwbuf;
    float* px[2]  = {px0,  px0  + (size_t)NNODE * H};
    float* plg[2] = {plg0, plg0 + (size_t)NEDGE * H};
    float* ze[4], * zn[4];
    for (int i = 0; i < 4; i++) {
        ze[i] = pzbase + (size_t)i * NEDGE * H;
        zn[i] = pznb + (size_t)i * NNODE * H;
    }

    const int* src_g = eig;  const int* dst_g = eig + NEDGE;
    const int* src_l = eil;  const int* dst_l = eil + NLG;

    // ===== stream 0: lg CSR + layer-0 edge khops + packs + init + node CSRs =====
    cudaMemsetAsync(pcnt, 0, NEDGE * sizeof(int), 0);
    hist_kernel<<<(NLG + 255) / 256, 256>>>(dst_l, pcnt, NLG);
    exclusive_scan(pcnt, rp_lg, pbs, NEDGE);
    cudaMemcpyAsync(pcur, rp_lg, NEDGE * sizeof(int), cudaMemcpyDeviceToDevice, 0);
    fill_kernel<<<(NLG + 255) / 256, 256>>>(dst_l, src_l, pcur, ci_lg, NLG);

    segsum_rel_kernel<<<(NEDGE + 7) / 8, 256>>>(rel, feat, rp_lg, ci_lg, ze[0], NEDGE);
    segsum_kernel<<<(NEDGE + 7) / 8, 256>>>(ze[0], rp_lg, ci_lg, ze[1], NEDGE);
    segsum_kernel<<<(NEDGE + 7) / 8, 256>>>(ze[1], rp_lg, ci_lg, ze[2], NEDGE);
    segsum_kernel<<<(NEDGE + 7) / 8, 256>>>(ze[2], rp_lg, ci_lg, ze[3], NEDGE);

    pack256_kernel<<<(4 * 16384 + 255) / 256, 256>>>(w_self, pwbuf + OFF_WSELF, 4);
    pack256_kernel<<<(16 * 16384 + 255) / 256, 256>>>(w_khop, pwbuf + OFF_WKHOP, 16);
    pack256_kernel<<<(4 * 16384 + 255) / 256, 256>>>(w_fuse, pwbuf + OFF_WFUSE, 4);
    packff1_kernel<<<(4 * 65536 + 255) / 256, 256>>>(w_ff1, pwbuf + OFF_WFF1, 4);
    packff2_kernel<<<(4 * 65536 + 255) / 256, 256>>>(w_ff2, pwbuf + OFF_WFF2, 4);

    cvt_kernel<<<(NNODE * H / 4 + 255) / 256, 256>>>(x_in, px[0], NNODE * H / 4);
    embed_kernel<<<NEDGE * 64 / 256, 256>>>(rel, feat, plg[0]);

    cudaMemsetAsync(pcnt, 0, NNODE * sizeof(int), 0);
    hist_kernel<<<(NEDGE + 255) / 256, 256>>>(dst_g, pcnt, NEDGE);
    exclusive_scan(pcnt, rp_nd, pbs, NNODE);
    cudaMemcpyAsync(pcur, rp_nd, NNODE * sizeof(int), cudaMemcpyDeviceToDevice, 0);
    fill_kernel<<<(NEDGE + 255) / 256, 256>>>(dst_g, src_g, pcur, ci_nd, NEDGE);

    cudaMemsetAsync(pcnt, 0, NNODE * sizeof(int), 0);
    hist_kernel<<<(NEDGE + 255) / 256, 256>>>(src_g, pcnt, NEDGE);
    hist_kernel<<<(NEDGE + 255) / 256, 256>>>(dst_g, pcnt, NEDGE);
    exclusive_scan(pcnt, rp_fn, pbs, NNODE);
    cudaMemcpyAsync(pcur, rp_fn, NNODE * sizeof(int), cudaMemcpyDeviceToDevice, 0);
    fill_kernel<<<(NEDGE + 255) / 256, 256>>>(src_g, nullptr, pcur, ci_fn, NEDGE);
    fill_kernel<<<(NEDGE + 255) / 256, 256>>>(dst_g, nullptr, pcur, ci_fn, NEDGE);

    cudaEventRecord(ev_init, 0);

    // ===== stream s2: node core, layer 0 =====
    cudaStreamWaitEvent(s2, ev_init, 0);
    segsum_kernel<<<(NNODE + 7) / 8, 256, 0, s2>>>(plg[0], rp_fn, ci_fn, pfn, NNODE);
    {
        const float* prev = px[0];
        for (int i = 0; i < 4; i++) {
            segsum_kernel<<<(NNODE + 7) / 8, 256, 0, s2>>>(prev, rp_nd, ci_nd, zn[i], NNODE);
            prev = zn[i];
        }
    }
    run_core(n, 0, 0, NNODE, zn, px[0], pfn, pout1n, px[1], 1, s2);
    cudaEventRecord(ev_x0, s2);

    // ===== stream 0: edge core, layer 0 =====
    gather2_kernel<<<NEDGE * 64 / 256, 256>>>(px[0], src_g, dst_g, pfe, NEDGE);
    run_core(n, 0, 1, NEDGE, ze, plg[0], pfe, pout1, plg[1], 1, (cudaStream_t)0);
    cudaEventRecord(ev_lg0, 0);

    // ===== stream s2: node core, layer 1 =====
    cudaStreamWaitEvent(s2, ev_lg0, 0);
    segsum_kernel<<<(NNODE + 7) / 8, 256, 0, s2>>>(plg[1], rp_fn, ci_fn, pfn, NNODE);
    {
        const float* prev = px[1];
        for (int i = 0; i < 4; i++) {
            segsum_kernel<<<(NNODE + 7) / 8, 256, 0, s2>>>(prev, rp_nd, ci_nd, zn[i], NNODE);
            prev = zn[i];
        }
    }
    run_core(n, 1, 0, NNODE, zn, px[1], pfn, pout1n, (float*)d_out, 0, s2);
    cudaEventRecord(ev_fin, s2);

    // ===== stream 0: edge core, layer 1 =====
    cudaStreamWaitEvent(0, ev_x0, 0);
    gather2_kernel<<<NEDGE * 64 / 256, 256>>>(px[1], src_g, dst_g, pfe, NEDGE);
    {
        const float* prev = plg[1];
        for (int i = 0; i < 4; i++) {
            segsum_kernel<<<(NEDGE + 7) / 8, 256>>>(prev, rp_lg, ci_lg, ze[i], NEDGE);
            prev = ze[i];
        }
    }
    run_core(n, 1, 1, NEDGE, ze, plg[1], pfe, pout1,
             (float*)d_out + (size_t)NNODE * H, 0, (cudaStream_t)0);

    cudaStreamWaitEvent(0, ev_fin, 0);
    (void)in_sizes; (void)n_in; (void)out_size;
}